// round 8
// baseline (speedup 1.0000x reference)
#include <cuda_runtime.h>
#include <math.h>

#define H_ 8
#define D_ 64
#define N_ 2
#define Q_ 128
#define P_ 128
#define B_ 4
#define ROWS_ 1024          // N_*Q_*B_ == N_*P_*B_
#define EPSF 1e-5f
#define TEMPF 30.0f

// k_bd dynamic smem: 2 stage-buffers x 4 arrays x [64][17] float4 + T[512] float4 + 32 floats
#define BD_ARR   (64 * 17)                    // float4 per array
#define BD_STAGE (4 * BD_ARR)                 // float4 per stage
#define SMEM_BD  ((2 * BD_STAGE + 512) * 16 + 128)

// ---------------- packed fp32x2 FMA (sm_103a FFMA2) ----------------
__device__ __forceinline__ void fma2(float2& d, float2 a, float2 b) {
    asm("fma.rn.f32x2 %0, %1, %2, %0;"
        : "+l"(reinterpret_cast<unsigned long long&>(d))
        : "l"(reinterpret_cast<unsigned long long&>(a)),
          "l"(reinterpret_cast<unsigned long long&>(b)));
}
__device__ __forceinline__ float2 dup2(float v) { return make_float2(v, v); }
__device__ __forceinline__ float2 neg2(float2 v) { return make_float2(-v.x, -v.y); }

__device__ __forceinline__ void cp_async16(unsigned dst_smem, const void* src) {
    asm volatile("cp.async.cg.shared.global [%0], [%1], 16;" :: "r"(dst_smem), "l"(src));
}

// ---------------- scratch (device globals; no allocation) ----------------
__device__ float  g_wk_r[H_][ROWS_][D_];   // RAW projections (pre-norm)
__device__ float  g_wk_i[H_][ROWS_][D_];
__device__ float  g_wq_r[H_][ROWS_][D_];
__device__ float  g_wq_i[H_][ROWS_][D_];
__device__ float  g_mean[4][H_][N_][64];   // a: 0 wk_r, 1 wk_i, 2 wq_r, 3 wq_i
__device__ float  g_rstd[4][H_][N_][64];
__device__ float4 g_T [ROWS_][32][16];     // per (n,q,b): 32 t-vectors of 64 floats
__device__ float  g_S4[ROWS_][H_][4];      // bias scalars s1..s4
__device__ float  g_S [H_][N_][Q_][B_][P_];// AC scores -> aff
__device__ float  g_S2[H_][N_][Q_][B_][P_];// BD magnitudes

// ---------------- kernel 1: complex projections, register-tiled ----------------
// grid (32 row-tiles of 32, H, 2{key,query}), block 256 = 16x16, thread 2row x 4d
__global__ __launch_bounds__(256) void k_proj(
    const float* __restrict__ kr, const float* __restrict__ ki,
    const float* __restrict__ qr, const float* __restrict__ qi,
    const float* __restrict__ WKr, const float* __restrict__ WKrb,
    const float* __restrict__ WKi, const float* __restrict__ WKib,
    const float* __restrict__ WQr, const float* __restrict__ WQrb,
    const float* __restrict__ WQi, const float* __restrict__ WQib)
{
    int h   = blockIdx.y;
    int isQ = blockIdx.z;
    const float* xr = isQ ? qr : kr;
    const float* xi = isQ ? qi : ki;
    const float* Wr = (isQ ? WQr : WKr) + h * D_ * D_;
    const float* Wi = (isQ ? WQi : WKi) + h * D_ * D_;
    const float* br = (isQ ? WQrb : WKrb) + h * D_;
    const float* bi = (isQ ? WQib : WKib) + h * D_;
    float* outR = isQ ? &g_wq_r[h][0][0] : &g_wk_r[h][0][0];
    float* outI = isQ ? &g_wq_i[h][0][0] : &g_wk_i[h][0][0];

    __shared__ float Wr_t[D_][66];   // [e][d]
    __shared__ float Wi_t[D_][66];
    __shared__ float Xr[32][D_], Xi[32][D_];

    int t = threadIdx.x;
    for (int i = t; i < D_ * D_; i += 256) {
        int d = i >> 6, e = i & 63;
        Wr_t[e][d] = Wr[i];
        Wi_t[e][d] = Wi[i];
    }
    int row0 = blockIdx.x * 32;
    const float4* xr4 = (const float4*)(xr + (size_t)row0 * D_);
    const float4* xi4 = (const float4*)(xi + (size_t)row0 * D_);
    for (int i = t; i < 32 * D_ / 4; i += 256) {
        ((float4*)Xr)[i] = xr4[i];
        ((float4*)Xi)[i] = xi4[i];
    }
    __syncthreads();

    int tx = t & 15, ty = t >> 4;
    int d0 = tx * 4, r0 = ty * 2;

    float2 ar[2][2], ai[2][2];
#pragma unroll
    for (int i = 0; i < 2; i++)
#pragma unroll
        for (int j = 0; j < 2; j++) { ar[i][j] = make_float2(0.f, 0.f); ai[i][j] = make_float2(0.f, 0.f); }

#pragma unroll 4
    for (int e = 0; e < 64; e++) {
        float2 wr0 = *(const float2*)&Wr_t[e][d0];
        float2 wr1 = *(const float2*)&Wr_t[e][d0 + 2];
        float2 wi0 = *(const float2*)&Wi_t[e][d0];
        float2 wi1 = *(const float2*)&Wi_t[e][d0 + 2];
        float2 nwi0 = neg2(wi0), nwi1 = neg2(wi1);
#pragma unroll
        for (int i = 0; i < 2; i++) {
            float2 v2r = dup2(Xr[r0 + i][e]);
            float2 v2i = dup2(Xi[r0 + i][e]);
            fma2(ar[i][0], v2r, wr0);  fma2(ar[i][0], v2i, nwi0);
            fma2(ar[i][1], v2r, wr1);  fma2(ar[i][1], v2i, nwi1);
            fma2(ai[i][0], v2r, wi0);  fma2(ai[i][0], v2i, wr0);
            fma2(ai[i][1], v2r, wi1);  fma2(ai[i][1], v2i, wr1);
        }
    }

    float2 bR0 = *(const float2*)&br[d0];
    float2 bR1 = *(const float2*)&br[d0 + 2];
    float2 bI0 = *(const float2*)&bi[d0];
    float2 bI1 = *(const float2*)&bi[d0 + 2];
#pragma unroll
    for (int i = 0; i < 2; i++) {
        ar[i][0].x += bR0.x - bI0.x;  ar[i][0].y += bR0.y - bI0.y;
        ar[i][1].x += bR1.x - bI1.x;  ar[i][1].y += bR1.y - bI1.y;
        ai[i][0].x += bR0.x + bI0.x;  ai[i][0].y += bR0.y + bI0.y;
        ai[i][1].x += bR1.x + bI1.x;  ai[i][1].y += bR1.y + bI1.y;
        float2* oR = (float2*)(outR + (size_t)(row0 + r0 + i) * D_ + d0);
        float2* oI = (float2*)(outI + (size_t)(row0 + r0 + i) * D_ + d0);
        oR[0] = ar[i][0];  oR[1] = ar[i][1];
        oI[0] = ai[i][0];  oI[1] = ai[i][1];
    }
}

// ---------------- kernel 2: instance-norm STATS only (no normalize pass) ----------------
// grid (N_, H_, 4), block 512
__global__ __launch_bounds__(512) void k_stats()
{
    int n = blockIdx.x, h = blockIdx.y, a = blockIdx.z;
    const float* base;
    if      (a == 0) base = &g_wk_r[0][0][0];
    else if (a == 1) base = &g_wk_i[0][0][0];
    else if (a == 2) base = &g_wq_r[0][0][0];
    else             base = &g_wq_i[0][0][0];
    const float* x = base + ((size_t)h * ROWS_ + (size_t)n * 512) * D_;

    int t = threadIdx.x;
    int d = t & 63, c = t >> 6;       // 8 chunks of 64 rows
    float s = 0.f, s2 = 0.f;
    for (int r = c * 64; r < (c + 1) * 64; r++) {
        float v = x[r * 64 + d];
        s += v; s2 += v * v;
    }
    __shared__ float Ss[8][64], S2s[8][64];
    Ss[c][d] = s; S2s[c][d] = s2;
    __syncthreads();
    if (t < 64) {
        float sum = 0.f, sum2 = 0.f;
#pragma unroll
        for (int cc = 0; cc < 8; cc++) { sum += Ss[cc][t]; sum2 += S2s[cc][t]; }
        float m   = sum * (1.f / 512.f);
        float var = sum2 * (1.f / 512.f) - m * m;
        g_mean[a][h][n][t] = m;
        g_rstd[a][h][n][t] = rsqrtf(var + EPSF);
    }
}

// ---------------- kernel 3: t-vectors (GEMM) + bias scalars (norm folded) ----------------
// grid (32 row-tiles of 32, H), block 256 = 16x16
__global__ __launch_bounds__(256) void k_tvec(
    const float* __restrict__ WKRr, const float* __restrict__ WKRrb,
    const float* __restrict__ WKRi, const float* __restrict__ WKRib,
    const float* __restrict__ wr_r_g, const float* __restrict__ wr_r_bt,
    const float* __restrict__ wr_i_g, const float* __restrict__ wr_i_bt)
{
    int h = blockIdx.y;
    int pt0 = blockIdx.x * 32;
    int n = pt0 >> 9;                 // rows 0..511 -> n=0, 512.. -> n=1
    __shared__ float Ur[32][D_], Ui[32][D_];
    __shared__ float Wr_s[64][66], Wi_s[64][66];   // [d][e]
    __shared__ float bm_s[64], bp_s[64];
    __shared__ float Ar_s[64], Cr_s[64], Ai_s[64], Ci_s[64];

    int t = threadIdx.x;
    const float* Wr = WKRr + h * D_ * D_;
    const float* Wi = WKRi + h * D_ * D_;
    for (int i = t; i < D_ * D_; i += 256) {
        int dd = i >> 6, e = i & 63;
        Wr_s[dd][e] = Wr[i];
        Wi_s[dd][e] = Wi[i];
    }
    if (t < 64) {
        float brv = WKRrb[h * D_ + t], biv = WKRib[h * D_ + t];
        bm_s[t] = brv - biv;
        bp_s[t] = brv + biv;
        float m2 = g_mean[2][h][n][t], r2 = g_rstd[2][h][n][t];
        float m3 = g_mean[3][h][n][t], r3 = g_rstd[3][h][n][t];
        float gr = wr_r_g[h * 64 + t], btr = wr_r_bt[h * 64 + t];
        float gi = wr_i_g[h * 64 + t], bti = wr_i_bt[h * 64 + t];
        Ar_s[t] = r2 * gr;  Cr_s[t] = btr - m2 * r2 * gr;
        Ai_s[t] = r3 * gi;  Ci_s[t] = bti - m3 * r3 * gi;
    }
    __syncthreads();
    for (int i = t; i < 32 * D_; i += 256) {
        int l = i >> 6, d = i & 63;
        Ur[l][d] = g_wq_r[h][pt0 + l][d] * Ar_s[d] + Cr_s[d];
        Ui[l][d] = g_wq_i[h][pt0 + l][d] * Ai_s[d] + Ci_s[d];
    }
    __syncthreads();

    int tx = t & 15, ty = t >> 4;
    int e0 = tx * 4, r0 = ty * 2;

    float2 t1[2][2], t2[2][2], t3[2][2], t4[2][2];
#pragma unroll
    for (int i = 0; i < 2; i++)
#pragma unroll
        for (int j = 0; j < 2; j++) {
            t1[i][j] = make_float2(0.f, 0.f); t2[i][j] = make_float2(0.f, 0.f);
            t3[i][j] = make_float2(0.f, 0.f); t4[i][j] = make_float2(0.f, 0.f);
        }

#pragma unroll 4
    for (int dd = 0; dd < 64; dd++) {
        float2 wr0 = *(const float2*)&Wr_s[dd][e0];
        float2 wr1 = *(const float2*)&Wr_s[dd][e0 + 2];
        float2 wi0 = *(const float2*)&Wi_s[dd][e0];
        float2 wi1 = *(const float2*)&Wi_s[dd][e0 + 2];
#pragma unroll
        for (int i = 0; i < 2; i++) {
            float2 u2r = dup2(Ur[r0 + i][dd]);
            float2 u2i = dup2(Ui[r0 + i][dd]);
            fma2(t1[i][0], u2r, wr0);  fma2(t1[i][1], u2r, wr1);
            fma2(t2[i][0], u2r, wi0);  fma2(t2[i][1], u2r, wi1);
            fma2(t3[i][0], u2i, wr0);  fma2(t3[i][1], u2i, wr1);
            fma2(t4[i][0], u2i, wi0);  fma2(t4[i][1], u2i, wi1);
        }
    }

#pragma unroll
    for (int i = 0; i < 2; i++) {
        float* base = (float*)&g_T[pt0 + r0 + i][h * 4][0];   // 4 vecs x 64 floats
        *(float2*)(base +   0 + e0) = t1[i][0];  *(float2*)(base +   0 + e0 + 2) = t1[i][1];
        *(float2*)(base +  64 + e0) = t2[i][0];  *(float2*)(base +  64 + e0 + 2) = t2[i][1];
        *(float2*)(base + 128 + e0) = t3[i][0];  *(float2*)(base + 128 + e0 + 2) = t3[i][1];
        *(float2*)(base + 192 + e0) = t4[i][0];  *(float2*)(base + 192 + e0 + 2) = t4[i][1];
    }

    if (tx == 0) {
#pragma unroll
        for (int i = 0; i < 2; i++) {
            float s1 = 0.f, s2v = 0.f, s3 = 0.f, s4 = 0.f;
            for (int dd = 0; dd < 64; dd++) {
                float u_r = Ur[r0 + i][dd], u_i = Ui[r0 + i][dd];
                float bm = bm_s[dd], bp = bp_s[dd];
                s1 += bm * u_r;  s2v += bp * u_i;
                s3 += bm * u_i;  s4 += bp * u_r;
            }
            int pt = pt0 + r0 + i;
            g_S4[pt][h][0] = s1;  g_S4[pt][h][1] = s2v;
            g_S4[pt][h][2] = s3;  g_S4[pt][h][3] = s4;
        }
    }
}

// ---------------- kernel 4: BD (hot loop) — cp.async double-buffered, Np=2 Nh=2 ----------------
// grid 1024 points (n,q,b), block 128: pbase(32) x hgroup(4). Each thread: p, p+32; 2 heads.
__global__ __launch_bounds__(128) void k_bd(
    const float4* __restrict__ emb_r4, const float4* __restrict__ emb_i4)
{
    int pt = blockIdx.x;
    int b  = pt & 3;
    int q  = (pt >> 2) & 127;
    int n  = pt >> 9;

    extern __shared__ float4 smem4[];
    float4* T_s = smem4 + 2 * BD_STAGE;       // [32][16]
    float*  s_s = (float*)(T_s + 512);

    int t = threadIdx.x;
    unsigned sbase = (unsigned)__cvta_generic_to_shared(smem4);
    unsigned tbase = (unsigned)__cvta_generic_to_shared(T_s);

    long rowE = ((long)n * 128 + q) * 128;    // + p
    long rowF = ((long)n * 128) * 128 + q;    // + p*128

    // issue both stages as two cp.async groups (stage0 + T first)
#pragma unroll
    for (int s = 0; s < 2; s++) {
        int p0 = s * 64;
        unsigned bufb = sbase + (unsigned)(s * BD_STAGE) * 16u;
#pragma unroll
        for (int k = 0; k < 8; k++) {
            int j  = t + k * 128;
            int pl = j >> 4, d4 = j & 15;
            long eIdx = ((rowE + p0 + pl) * 4 + b) * 16 + d4;
            long fIdx = ((rowF + (long)(p0 + pl) * 128) * 4 + b) * 16 + d4;
            unsigned off = (unsigned)(pl * 17 + d4) * 16u;
            cp_async16(bufb + 0 * BD_ARR * 16u + off, emb_r4 + eIdx);
            cp_async16(bufb + 1 * BD_ARR * 16u + off, emb_i4 + eIdx);
            cp_async16(bufb + 2 * BD_ARR * 16u + off, emb_r4 + fIdx);
            cp_async16(bufb + 3 * BD_ARR * 16u + off, emb_i4 + fIdx);
        }
        if (s == 0) {
            const float4* Tg = &g_T[pt][0][0];
#pragma unroll
            for (int k = 0; k < 4; k++) {
                int j = t + k * 128;
                cp_async16(tbase + (unsigned)j * 16u, Tg + j);
            }
        }
        asm volatile("cp.async.commit_group;" ::: "memory");
    }
    if (t < 32) s_s[t] = ((const float*)&g_S4[pt][0][0])[t];

    int pbase = t & 31;
    int hg    = t >> 5;           // 0..3
    int h0    = hg * 2;

#pragma unroll
    for (int stage = 0; stage < 2; stage++) {
        if (stage == 0) asm volatile("cp.async.wait_group 1;" ::: "memory");
        else            asm volatile("cp.async.wait_group 0;" ::: "memory");
        __syncthreads();

        const float4* Er_s = smem4 + stage * BD_STAGE;
        const float4* Ei_s = Er_s + BD_ARR;
        const float4* Fr_s = Ei_s + BD_ARR;
        const float4* Fi_s = Fr_s + BD_ARR;
        int p0 = stage * 64;

        // accums [pi][hl]: rP, rM, iP, iM (merged a/b halves)
        float2 rP[2][2], rM[2][2], iP[2][2], iM[2][2];
#pragma unroll
        for (int pi = 0; pi < 2; pi++)
#pragma unroll
            for (int hl = 0; hl < 2; hl++) {
                rP[pi][hl] = make_float2(0.f, 0.f); rM[pi][hl] = make_float2(0.f, 0.f);
                iP[pi][hl] = make_float2(0.f, 0.f); iM[pi][hl] = make_float2(0.f, 0.f);
            }

#pragma unroll 4
        for (int d4 = 0; d4 < 16; d4++) {
            float4 er[2], ei[2], fr[2], fi[2];
#pragma unroll
            for (int pi = 0; pi < 2; pi++) {
                int pp = pbase + 32 * pi;
                er[pi] = Er_s[pp * 17 + d4];
                ei[pi] = Ei_s[pp * 17 + d4];
                fr[pi] = Fr_s[pp * 17 + d4];
                fi[pi] = Fi_s[pp * 17 + d4];
            }
#pragma unroll
            for (int hl = 0; hl < 2; hl++) {
                int hv = h0 + hl;
                float4 T1 = T_s[(4 * hv + 0) * 16 + d4];
                float4 T2 = T_s[(4 * hv + 1) * 16 + d4];
                float4 T3 = T_s[(4 * hv + 2) * 16 + d4];
                float4 T4 = T_s[(4 * hv + 3) * 16 + d4];
                float2 T1a = make_float2(T1.x, T1.y), T1b = make_float2(T1.z, T1.w);
                float2 T2a = make_float2(T2.x, T2.y), T2b = make_float2(T2.z, T2.w);
                float2 T3a = make_float2(T3.x, T3.y), T3b = make_float2(T3.z, T3.w);
                float2 T4a = make_float2(T4.x, T4.y), T4b = make_float2(T4.z, T4.w);
#pragma unroll
                for (int pi = 0; pi < 2; pi++) {
                    float2 er_a = make_float2(er[pi].x, er[pi].y), er_b = make_float2(er[pi].z, er[pi].w);
                    float2 ei_a = make_float2(ei[pi].x, ei[pi].y), ei_b = make_float2(ei[pi].z, ei[pi].w);
                    float2 fr_a = make_float2(fr[pi].x, fr[pi].y), fr_b = make_float2(fr[pi].z, fr[pi].w);
                    float2 fi_a = make_float2(fi[pi].x, fi[pi].y), fi_b = make_float2(fi[pi].z, fi[pi].w);
                    fma2(rP[pi][hl], er_a, T1a);  fma2(rP[pi][hl], er_b, T1b);
                    fma2(rM[pi][hl], ei_a, T2a);  fma2(rM[pi][hl], ei_b, T2b);
                    fma2(rM[pi][hl], fr_a, T4a);  fma2(rM[pi][hl], fr_b, T4b);
                    fma2(rM[pi][hl], fi_a, T3a);  fma2(rM[pi][hl], fi_b, T3b);
                    fma2(iP[pi][hl], er_a, T3a);  fma2(iP[pi][hl], er_b, T3b);
                    fma2(iP[pi][hl], fr_a, T2a);  fma2(iP[pi][hl], fr_b, T2b);
                    fma2(iP[pi][hl], fi_a, T1a);  fma2(iP[pi][hl], fi_b, T1b);
                    fma2(iM[pi][hl], ei_a, T4a);  fma2(iM[pi][hl], ei_b, T4b);
                }
            }
        }

#pragma unroll
        for (int pi = 0; pi < 2; pi++)
#pragma unroll
            for (int hl = 0; hl < 2; hl++) {
                int hv = h0 + hl;
                float r  = (rP[pi][hl].x + rP[pi][hl].y) - (rM[pi][hl].x + rM[pi][hl].y)
                         + s_s[hv * 4 + 0] - s_s[hv * 4 + 1];
                float iv = (iP[pi][hl].x + iP[pi][hl].y) - (iM[pi][hl].x + iM[pi][hl].y)
                         + s_s[hv * 4 + 2] + s_s[hv * 4 + 3];
                g_S2[hv][n][q][b][p0 + pbase + 32 * pi] = sqrtf(r * r + iv * iv);
            }
    }
}

// ---------------- kernel 5: AC magnitudes, interleaved-k complex GEMM ----------------
// grid (8 = qt(4)*pt(2), B, H*N), block 256: tx(32)->p, ty(8)->4q. Norm folded.
__global__ __launch_bounds__(256) void k_ac(
    const float* __restrict__ ww_r_g, const float* __restrict__ ww_r_bt,
    const float* __restrict__ ww_i_g, const float* __restrict__ ww_i_bt)
{
    int b = blockIdx.y;
    int h = blockIdx.z / N_, n = blockIdx.z % N_;
    int pt = blockIdx.x & 1, qt = blockIdx.x >> 1;
    int q0 = qt * 32, p0 = pt * 64;

    __shared__ float2 kT[64][65];                // [d][p] interleaved (kr,ki)
    __shared__ float  qrT[64][34], qiT[64][34];  // [d][q]
    __shared__ float  Akr[64], Ckr[64], Aki[64], Cki[64];
    __shared__ float  Aqr[64], Cqr[64], Aqi[64], Cqi[64];

    int t = threadIdx.x;
    if (t < 64) {
        int d = t;
        float m0 = g_mean[0][h][n][d], r0s = g_rstd[0][h][n][d];
        float m1 = g_mean[1][h][n][d], r1s = g_rstd[1][h][n][d];
        Akr[d] = r0s;  Ckr[d] = -m0 * r0s;
        Aki[d] = r1s;  Cki[d] = -m1 * r1s;
        float m2 = g_mean[2][h][n][d], r2s = g_rstd[2][h][n][d];
        float m3 = g_mean[3][h][n][d], r3s = g_rstd[3][h][n][d];
        float gr = ww_r_g[h * 64 + d], btr = ww_r_bt[h * 64 + d];
        float gi = ww_i_g[h * 64 + d], bti = ww_i_bt[h * 64 + d];
        Aqr[d] = r2s * gr;  Cqr[d] = btr - m2 * r2s * gr;
        Aqi[d] = r3s * gi;  Cqi[d] = bti - m3 * r3s * gi;
    }
    __syncthreads();

    for (int i = t; i < 64 * 64; i += 256) {
        int p = i >> 6, d = i & 63;
        int row = (n * P_ + p0 + p) * B_ + b;
        float xr = g_wk_r[h][row][d];
        float xi = g_wk_i[h][row][d];
        kT[d][p] = make_float2(xr * Akr[d] + Ckr[d], xi * Aki[d] + Cki[d]);
    }
    for (int i = t; i < 32 * 64; i += 256) {
        int q = i >> 6, d = i & 63;
        int row = (n * Q_ + q0 + q) * B_ + b;
        qrT[d][q] = g_wq_r[h][row][d] * Aqr[d] + Cqr[d];
        qiT[d][q] = g_wq_i[h][row][d] * Aqi[d] + Cqi[d];
    }
    __syncthreads();

    int tx = t & 31, ty = t >> 5;
    int lq0 = ty * 4;

    float2 accR[2][2], accI[2][2];   // [q-pair ii][p j], p_j = tx + 32*j
#pragma unroll
    for (int ii = 0; ii < 2; ii++)
#pragma unroll
        for (int j = 0; j < 2; j++) { accR[ii][j] = make_float2(0.f, 0.f); accI[ii][j] = make_float2(0.f, 0.f); }

#pragma unroll 4
    for (int d = 0; d < 64; d++) {
        float2 kv0 = kT[d][tx];
        float2 kv1 = kT[d][tx + 32];
        float2 qr20 = *(const float2*)&qrT[d][lq0];
        float2 qr21 = *(const float2*)&qrT[d][lq0 + 2];
        float2 qi20 = *(const float2*)&qiT[d][lq0];
        float2 qi21 = *(const float2*)&qiT[d][lq0 + 2];
        float2 nqi20 = neg2(qi20), nqi21 = neg2(qi21);
        {
            float2 kr2 = dup2(kv0.x), ki2 = dup2(kv0.y);
            fma2(accR[0][0], qr20, kr2);  fma2(accR[0][0], nqi20, ki2);
            fma2(accI[0][0], qr20, ki2);  fma2(accI[0][0], qi20,  kr2);
            fma2(accR[1][0], qr21, kr2);  fma2(accR[1][0], nqi21, ki2);
            fma2(accI[1][0], qr21, ki2);  fma2(accI[1][0], qi21,  kr2);
        }
        {
            float2 kr2 = dup2(kv1.x), ki2 = dup2(kv1.y);
            fma2(accR[0][1], qr20, kr2);  fma2(accR[0][1], nqi20, ki2);
            fma2(accI[0][1], qr20, ki2);  fma2(accI[0][1], qi20,  kr2);
            fma2(accR[1][1], qr21, kr2);  fma2(accR[1][1], nqi21, ki2);
            fma2(accI[1][1], qr21, ki2);  fma2(accI[1][1], qi21,  kr2);
        }
    }

#pragma unroll
    for (int ii = 0; ii < 2; ii++)
#pragma unroll
        for (int j = 0; j < 2; j++) {
            int qg = q0 + lq0 + 2 * ii;
            int p  = p0 + tx + 32 * j;
            float r0v = accR[ii][j].x, i0v = accI[ii][j].x;
            float r1v = accR[ii][j].y, i1v = accI[ii][j].y;
            g_S[h][n][qg][b][p]     = sqrtf(r0v * r0v + i0v * i0v);
            g_S[h][n][qg + 1][b][p] = sqrtf(r1v * r1v + i1v * i1v);
        }
}

// ---------------- kernel 6: softmax over b (sums AC + BD) ----------------
__global__ __launch_bounds__(256) void k_softmax()
{
    int idx = blockIdx.x * 256 + threadIdx.x;
    int p  = idx % P_;
    int q  = (idx / P_) % Q_;
    int hn = idx / (P_ * Q_);
    size_t off = (((size_t)hn * Q_ + q) * B_) * P_ + p;
    float* baseA = &g_S[0][0][0][0][0] + off;
    const float* baseB = &g_S2[0][0][0][0][0] + off;
    float v0 = (baseA[0 * P_] + baseB[0 * P_]) * TEMPF;
    float v1 = (baseA[1 * P_] + baseB[1 * P_]) * TEMPF;
    float v2 = (baseA[2 * P_] + baseB[2 * P_]) * TEMPF;
    float v3 = (baseA[3 * P_] + baseB[3 * P_]) * TEMPF;
    float m = fmaxf(fmaxf(v0, v1), fmaxf(v2, v3));
    v0 = __expf(v0 - m); v1 = __expf(v1 - m); v2 = __expf(v2 - m); v3 = __expf(v3 - m);
    float inv = 1.f / (v0 + v1 + v2 + v3);
    baseA[0 * P_] = v0 * inv;
    baseA[1 * P_] = v1 * inv;
    baseA[2 * P_] = v2 * inv;
    baseA[3 * P_] = v3 * inv;
}

// ---------------- kernel 7: output aggregation (GEMM per (h,n,b,q-tile)) ----------------
// grid (4 q-tiles of 32, B, H*N), block 256: tx(16)->4d, ty(16)->2q
__global__ __launch_bounds__(256) void k_out(
    const float* __restrict__ vr, const float* __restrict__ vi,
    float* __restrict__ out)
{
    int b = blockIdx.y;
    int h = blockIdx.z / N_, n = blockIdx.z % N_;
    int q0 = blockIdx.x * 32;

    __shared__ float aff_s[32][64];          // [q][p-chunk]
    __shared__ float vr_s[64][D_], vi_s[64][D_];

    int t = threadIdx.x;
    int tx = t & 15, ty = t >> 4;
    int d0 = tx * 4, lq0 = ty * 2;

    float2 cr[2][2], ci[2][2];
#pragma unroll
    for (int i = 0; i < 2; i++)
#pragma unroll
        for (int j = 0; j < 2; j++) { cr[i][j] = make_float2(0.f, 0.f); ci[i][j] = make_float2(0.f, 0.f); }

    for (int c = 0; c < 2; c++) {
        __syncthreads();
        int p0 = c * 64;
        for (int i = t; i < 32 * 64; i += 256) {
            int lq = i >> 6, pp = i & 63;
            aff_s[lq][pp] = g_S[h][n][q0 + lq][b][p0 + pp];
        }
        for (int i = t; i < 64 * D_; i += 256) {
            int pp = i >> 6, d = i & 63;
            size_t off = (((size_t)n * P_ + p0 + pp) * B_ + b) * D_ + d;
            vr_s[pp][d] = vr[off];
            vi_s[pp][d] = vi[off];
        }
        __syncthreads();

#pragma unroll 4
        for (int pp = 0; pp < 64; pp++) {
            float2 v_r0 = *(const float2*)&vr_s[pp][d0];
            float2 v_r1 = *(const float2*)&vr_s[pp][d0 + 2];
            float2 v_i0 = *(const float2*)&vi_s[pp][d0];
            float2 v_i1 = *(const float2*)&vi_s[pp][d0 + 2];
#pragma unroll
            for (int i = 0; i < 2; i++) {
                float2 a2 = dup2(aff_s[lq0 + i][pp]);
                fma2(cr[i][0], a2, v_r0);  fma2(cr[i][1], a2, v_r1);
                fma2(ci[i][0], a2, v_i0);  fma2(ci[i][1], a2, v_i1);
            }
        }
    }

#pragma unroll
    for (int i = 0; i < 2; i++) {
        int qg = q0 + lq0 + i;
        size_t o = (((size_t)n * Q_ + qg) * B_ + b) * (H_ * D_) + h * D_ + d0;
        *(float2*)(out + o)     = cr[i][0];
        *(float2*)(out + o + 2) = cr[i][1];
        size_t oi = o + (size_t)N_ * Q_ * B_ * H_ * D_;
        *(float2*)(out + oi)     = ci[i][0];
        *(float2*)(out + oi + 2) = ci[i][1];
    }
}

// ---------------- launch ----------------
extern "C" void kernel_launch(void* const* d_in, const int* in_sizes, int n_in,
                              void* d_out, int out_size)
{
    const float* query_r = (const float*)d_in[0];
    const float* query_i = (const float*)d_in[1];
    const float* key_r   = (const float*)d_in[2];
    const float* key_i   = (const float*)d_in[3];
    const float* val_r   = (const float*)d_in[4];
    const float* val_i   = (const float*)d_in[5];
    const float* emb_r   = (const float*)d_in[6];
    const float* emb_i   = (const float*)d_in[7];
    const float* WKr_w   = (const float*)d_in[8];
    const float* WKr_b   = (const float*)d_in[9];
    const float* WKi_w   = (const float*)d_in[10];
    const float* WKi_b   = (const float*)d_in[11];
    const float* WKRr_w  = (const float*)d_in[12];
    const float* WKRr_b  = (const float*)d_in[13];
    const float* WKRi_w  = (const float*)d_in[14];
    const float* WKRi_b  = (const float*)d_in[15];
    const float* WQr_w   = (const float*)d_in[16];
    const float* WQr_b   = (const float*)d_in[17];
    const float* WQi_w   = (const float*)d_in[18];
    const float* WQi_b   = (const float*)d_in[19];
    const float* ww_r_g  = (const float*)d_in[20];
    const float* ww_r_bt = (const float*)d_in[21];
    const float* ww_i_g  = (const float*)d_in[22];
    const float* ww_i_bt = (const float*)d_in[23];
    const float* wr_r_g  = (const float*)d_in[24];
    const float* wr_r_bt = (const float*)d_in[25];
    const float* wr_i_g  = (const float*)d_in[26];
    const float* wr_i_bt = (const float*)d_in[27];

    cudaFuncSetAttribute(k_bd, cudaFuncAttributeMaxDynamicSharedMemorySize, SMEM_BD);

    k_proj<<<dim3(32, H_, 2), 256>>>(key_r, key_i, query_r, query_i,
                                     WKr_w, WKr_b, WKi_w, WKi_b,
                                     WQr_w, WQr_b, WQi_w, WQi_b);
    k_stats<<<dim3(N_, H_, 4), 512>>>();
    k_tvec<<<dim3(32, H_), 256>>>(WKRr_w, WKRr_b, WKRi_w, WKRi_b,
                                  wr_r_g, wr_r_bt, wr_i_g, wr_i_bt);
    k_bd<<<ROWS_, 128, SMEM_BD>>>((const float4*)emb_r, (const float4*)emb_i);
    k_ac<<<dim3(8, B_, H_ * N_), 256>>>(ww_r_g, ww_r_bt, ww_i_g, ww_i_bt);
    k_softmax<<<1024, 256>>>();
    k_out<<<dim3(4, B_, H_ * N_), 256>>>(val_r, val_i, (float*)d_out);
}

// round 9
// speedup vs baseline: 1.0697x; 1.0697x over previous
#include <cuda_runtime.h>
#include <math.h>

#define H_ 8
#define D_ 64
#define N_ 2
#define Q_ 128
#define P_ 128
#define B_ 4
#define ROWS_ 1024          // N_*Q_*B_ == N_*P_*B_
#define EPSF 1e-5f
#define TEMPF 30.0f

// k_bd dynamic smem: ONE stage buffer (4 arrays x [64][17] float4) + T[512] float4 + 32 floats
#define BD_ARR   (64 * 17)                    // float4 per array
#define BD_STAGE (4 * BD_ARR)                 // float4 per stage
#define SMEM_BD  ((BD_STAGE + 512) * 16 + 128)

// ---------------- packed fp32x2 FMA (sm_103a FFMA2) ----------------
__device__ __forceinline__ void fma2(float2& d, float2 a, float2 b) {
    asm("fma.rn.f32x2 %0, %1, %2, %0;"
        : "+l"(reinterpret_cast<unsigned long long&>(d))
        : "l"(reinterpret_cast<unsigned long long&>(a)),
          "l"(reinterpret_cast<unsigned long long&>(b)));
}
__device__ __forceinline__ float2 dup2(float v) { return make_float2(v, v); }
__device__ __forceinline__ float2 neg2(float2 v) { return make_float2(-v.x, -v.y); }

__device__ __forceinline__ void cp_async16(unsigned dst_smem, const void* src) {
    asm volatile("cp.async.cg.shared.global [%0], [%1], 16;" :: "r"(dst_smem), "l"(src));
}

// ---------------- scratch (device globals; no allocation) ----------------
__device__ float  g_wk_r[H_][ROWS_][D_];   // RAW projections (pre-norm)
__device__ float  g_wk_i[H_][ROWS_][D_];
__device__ float  g_wq_r[H_][ROWS_][D_];
__device__ float  g_wq_i[H_][ROWS_][D_];
__device__ float  g_mean[4][H_][N_][64];   // a: 0 wk_r, 1 wk_i, 2 wq_r, 3 wq_i
__device__ float  g_rstd[4][H_][N_][64];
__device__ float4 g_T [ROWS_][32][16];     // per (n,q,b): 32 t-vectors of 64 floats
__device__ float  g_S4[ROWS_][H_][4];      // bias scalars s1..s4
__device__ float  g_S [H_][N_][Q_][B_][P_];// AC scores -> aff
__device__ float  g_S2[H_][N_][Q_][B_][P_];// BD magnitudes

// ---------------- kernel 1: complex projections, register-tiled ----------------
// grid (32 row-tiles of 32, H, 2{key,query}), block 256 = 16x16, thread 2row x 4d
__global__ __launch_bounds__(256) void k_proj(
    const float* __restrict__ kr, const float* __restrict__ ki,
    const float* __restrict__ qr, const float* __restrict__ qi,
    const float* __restrict__ WKr, const float* __restrict__ WKrb,
    const float* __restrict__ WKi, const float* __restrict__ WKib,
    const float* __restrict__ WQr, const float* __restrict__ WQrb,
    const float* __restrict__ WQi, const float* __restrict__ WQib)
{
    int h   = blockIdx.y;
    int isQ = blockIdx.z;
    const float* xr = isQ ? qr : kr;
    const float* xi = isQ ? qi : ki;
    const float* Wr = (isQ ? WQr : WKr) + h * D_ * D_;
    const float* Wi = (isQ ? WQi : WKi) + h * D_ * D_;
    const float* br = (isQ ? WQrb : WKrb) + h * D_;
    const float* bi = (isQ ? WQib : WKib) + h * D_;
    float* outR = isQ ? &g_wq_r[h][0][0] : &g_wk_r[h][0][0];
    float* outI = isQ ? &g_wq_i[h][0][0] : &g_wk_i[h][0][0];

    __shared__ float Wr_t[D_][66];   // [e][d]
    __shared__ float Wi_t[D_][66];
    __shared__ float Xr[32][D_], Xi[32][D_];

    int t = threadIdx.x;
    for (int i = t; i < D_ * D_; i += 256) {
        int d = i >> 6, e = i & 63;
        Wr_t[e][d] = Wr[i];
        Wi_t[e][d] = Wi[i];
    }
    int row0 = blockIdx.x * 32;
    const float4* xr4 = (const float4*)(xr + (size_t)row0 * D_);
    const float4* xi4 = (const float4*)(xi + (size_t)row0 * D_);
    for (int i = t; i < 32 * D_ / 4; i += 256) {
        ((float4*)Xr)[i] = xr4[i];
        ((float4*)Xi)[i] = xi4[i];
    }
    __syncthreads();

    int tx = t & 15, ty = t >> 4;
    int d0 = tx * 4, r0 = ty * 2;

    float2 ar[2][2], ai[2][2];
#pragma unroll
    for (int i = 0; i < 2; i++)
#pragma unroll
        for (int j = 0; j < 2; j++) { ar[i][j] = make_float2(0.f, 0.f); ai[i][j] = make_float2(0.f, 0.f); }

#pragma unroll 4
    for (int e = 0; e < 64; e++) {
        float2 wr0 = *(const float2*)&Wr_t[e][d0];
        float2 wr1 = *(const float2*)&Wr_t[e][d0 + 2];
        float2 wi0 = *(const float2*)&Wi_t[e][d0];
        float2 wi1 = *(const float2*)&Wi_t[e][d0 + 2];
        float2 nwi0 = neg2(wi0), nwi1 = neg2(wi1);
#pragma unroll
        for (int i = 0; i < 2; i++) {
            float2 v2r = dup2(Xr[r0 + i][e]);
            float2 v2i = dup2(Xi[r0 + i][e]);
            fma2(ar[i][0], v2r, wr0);  fma2(ar[i][0], v2i, nwi0);
            fma2(ar[i][1], v2r, wr1);  fma2(ar[i][1], v2i, nwi1);
            fma2(ai[i][0], v2r, wi0);  fma2(ai[i][0], v2i, wr0);
            fma2(ai[i][1], v2r, wi1);  fma2(ai[i][1], v2i, wr1);
        }
    }

    float2 bR0 = *(const float2*)&br[d0];
    float2 bR1 = *(const float2*)&br[d0 + 2];
    float2 bI0 = *(const float2*)&bi[d0];
    float2 bI1 = *(const float2*)&bi[d0 + 2];
#pragma unroll
    for (int i = 0; i < 2; i++) {
        ar[i][0].x += bR0.x - bI0.x;  ar[i][0].y += bR0.y - bI0.y;
        ar[i][1].x += bR1.x - bI1.x;  ar[i][1].y += bR1.y - bI1.y;
        ai[i][0].x += bR0.x + bI0.x;  ai[i][0].y += bR0.y + bI0.y;
        ai[i][1].x += bR1.x + bI1.x;  ai[i][1].y += bR1.y + bI1.y;
        float2* oR = (float2*)(outR + (size_t)(row0 + r0 + i) * D_ + d0);
        float2* oI = (float2*)(outI + (size_t)(row0 + r0 + i) * D_ + d0);
        oR[0] = ar[i][0];  oR[1] = ar[i][1];
        oI[0] = ai[i][0];  oI[1] = ai[i][1];
    }
}

// ---------------- kernel 2: instance-norm STATS only (no normalize pass) ----------------
// grid (N_, H_, 4), block 512
__global__ __launch_bounds__(512) void k_stats()
{
    int n = blockIdx.x, h = blockIdx.y, a = blockIdx.z;
    const float* base;
    if      (a == 0) base = &g_wk_r[0][0][0];
    else if (a == 1) base = &g_wk_i[0][0][0];
    else if (a == 2) base = &g_wq_r[0][0][0];
    else             base = &g_wq_i[0][0][0];
    const float* x = base + ((size_t)h * ROWS_ + (size_t)n * 512) * D_;

    int t = threadIdx.x;
    int d = t & 63, c = t >> 6;       // 8 chunks of 64 rows
    float s = 0.f, s2 = 0.f;
    for (int r = c * 64; r < (c + 1) * 64; r++) {
        float v = x[r * 64 + d];
        s += v; s2 += v * v;
    }
    __shared__ float Ss[8][64], S2s[8][64];
    Ss[c][d] = s; S2s[c][d] = s2;
    __syncthreads();
    if (t < 64) {
        float sum = 0.f, sum2 = 0.f;
#pragma unroll
        for (int cc = 0; cc < 8; cc++) { sum += Ss[cc][t]; sum2 += S2s[cc][t]; }
        float m   = sum * (1.f / 512.f);
        float var = sum2 * (1.f / 512.f) - m * m;
        g_mean[a][h][n][t] = m;
        g_rstd[a][h][n][t] = rsqrtf(var + EPSF);
    }
}

// ---------------- kernel 3: t-vectors (GEMM) + bias scalars (norm folded) ----------------
// grid (32 row-tiles of 32, H), block 256 = 16x16
__global__ __launch_bounds__(256) void k_tvec(
    const float* __restrict__ WKRr, const float* __restrict__ WKRrb,
    const float* __restrict__ WKRi, const float* __restrict__ WKRib,
    const float* __restrict__ wr_r_g, const float* __restrict__ wr_r_bt,
    const float* __restrict__ wr_i_g, const float* __restrict__ wr_i_bt)
{
    int h = blockIdx.y;
    int pt0 = blockIdx.x * 32;
    int n = pt0 >> 9;                 // rows 0..511 -> n=0, 512.. -> n=1
    __shared__ float Ur[32][D_], Ui[32][D_];
    __shared__ float Wr_s[64][66], Wi_s[64][66];   // [d][e]
    __shared__ float bm_s[64], bp_s[64];
    __shared__ float Ar_s[64], Cr_s[64], Ai_s[64], Ci_s[64];

    int t = threadIdx.x;
    const float* Wr = WKRr + h * D_ * D_;
    const float* Wi = WKRi + h * D_ * D_;
    for (int i = t; i < D_ * D_; i += 256) {
        int dd = i >> 6, e = i & 63;
        Wr_s[dd][e] = Wr[i];
        Wi_s[dd][e] = Wi[i];
    }
    if (t < 64) {
        float brv = WKRrb[h * D_ + t], biv = WKRib[h * D_ + t];
        bm_s[t] = brv - biv;
        bp_s[t] = brv + biv;
        float m2 = g_mean[2][h][n][t], r2 = g_rstd[2][h][n][t];
        float m3 = g_mean[3][h][n][t], r3 = g_rstd[3][h][n][t];
        float gr = wr_r_g[h * 64 + t], btr = wr_r_bt[h * 64 + t];
        float gi = wr_i_g[h * 64 + t], bti = wr_i_bt[h * 64 + t];
        Ar_s[t] = r2 * gr;  Cr_s[t] = btr - m2 * r2 * gr;
        Ai_s[t] = r3 * gi;  Ci_s[t] = bti - m3 * r3 * gi;
    }
    __syncthreads();
    for (int i = t; i < 32 * D_; i += 256) {
        int l = i >> 6, d = i & 63;
        Ur[l][d] = g_wq_r[h][pt0 + l][d] * Ar_s[d] + Cr_s[d];
        Ui[l][d] = g_wq_i[h][pt0 + l][d] * Ai_s[d] + Ci_s[d];
    }
    __syncthreads();

    int tx = t & 15, ty = t >> 4;
    int e0 = tx * 4, r0 = ty * 2;

    float2 t1[2][2], t2[2][2], t3[2][2], t4[2][2];
#pragma unroll
    for (int i = 0; i < 2; i++)
#pragma unroll
        for (int j = 0; j < 2; j++) {
            t1[i][j] = make_float2(0.f, 0.f); t2[i][j] = make_float2(0.f, 0.f);
            t3[i][j] = make_float2(0.f, 0.f); t4[i][j] = make_float2(0.f, 0.f);
        }

#pragma unroll 4
    for (int dd = 0; dd < 64; dd++) {
        float2 wr0 = *(const float2*)&Wr_s[dd][e0];
        float2 wr1 = *(const float2*)&Wr_s[dd][e0 + 2];
        float2 wi0 = *(const float2*)&Wi_s[dd][e0];
        float2 wi1 = *(const float2*)&Wi_s[dd][e0 + 2];
#pragma unroll
        for (int i = 0; i < 2; i++) {
            float2 u2r = dup2(Ur[r0 + i][dd]);
            float2 u2i = dup2(Ui[r0 + i][dd]);
            fma2(t1[i][0], u2r, wr0);  fma2(t1[i][1], u2r, wr1);
            fma2(t2[i][0], u2r, wi0);  fma2(t2[i][1], u2r, wi1);
            fma2(t3[i][0], u2i, wr0);  fma2(t3[i][1], u2i, wr1);
            fma2(t4[i][0], u2i, wi0);  fma2(t4[i][1], u2i, wi1);
        }
    }

#pragma unroll
    for (int i = 0; i < 2; i++) {
        float* base = (float*)&g_T[pt0 + r0 + i][h * 4][0];   // 4 vecs x 64 floats
        *(float2*)(base +   0 + e0) = t1[i][0];  *(float2*)(base +   0 + e0 + 2) = t1[i][1];
        *(float2*)(base +  64 + e0) = t2[i][0];  *(float2*)(base +  64 + e0 + 2) = t2[i][1];
        *(float2*)(base + 128 + e0) = t3[i][0];  *(float2*)(base + 128 + e0 + 2) = t3[i][1];
        *(float2*)(base + 192 + e0) = t4[i][0];  *(float2*)(base + 192 + e0 + 2) = t4[i][1];
    }

    if (tx == 0) {
#pragma unroll
        for (int i = 0; i < 2; i++) {
            float s1 = 0.f, s2v = 0.f, s3 = 0.f, s4 = 0.f;
            for (int dd = 0; dd < 64; dd++) {
                float u_r = Ur[r0 + i][dd], u_i = Ui[r0 + i][dd];
                float bm = bm_s[dd], bp = bp_s[dd];
                s1 += bm * u_r;  s2v += bp * u_i;
                s3 += bm * u_i;  s4 += bp * u_r;
            }
            int pt = pt0 + r0 + i;
            g_S4[pt][h][0] = s1;  g_S4[pt][h][1] = s2v;
            g_S4[pt][h][2] = s3;  g_S4[pt][h][3] = s4;
        }
    }
}

// ---------------- kernel 4: BD (hot loop) — 256 thr, single buffer, cp.async, 2 CTA/SM ----------------
// grid 1024 points (n,q,b), block 256: p(64) x hgroup(4), 2 heads per thread. Two 64-p stages.
__global__ __launch_bounds__(256) void k_bd(
    const float4* __restrict__ emb_r4, const float4* __restrict__ emb_i4)
{
    int pt = blockIdx.x;
    int b  = pt & 3;
    int q  = (pt >> 2) & 127;
    int n  = pt >> 9;

    extern __shared__ float4 smem4[];
    float4* T_s = smem4 + BD_STAGE;           // [32][16]
    float*  s_s = (float*)(T_s + 512);

    int t = threadIdx.x;
    unsigned sbase = (unsigned)__cvta_generic_to_shared(smem4);
    unsigned tbase = (unsigned)__cvta_generic_to_shared(T_s);

    long rowE = ((long)n * 128 + q) * 128;    // + p
    long rowF = ((long)n * 128) * 128 + q;    // + p*128

    // issue stage-0 + T loads via cp.async
#pragma unroll
    for (int k = 0; k < 4; k++) {
        int j  = t + k * 256;
        int pl = j >> 4, d4 = j & 15;
        long eIdx = ((rowE + pl) * 4 + b) * 16 + d4;
        long fIdx = ((rowF + (long)pl * 128) * 4 + b) * 16 + d4;
        unsigned off = (unsigned)(pl * 17 + d4) * 16u;
        cp_async16(sbase + 0 * BD_ARR * 16u + off, emb_r4 + eIdx);
        cp_async16(sbase + 1 * BD_ARR * 16u + off, emb_i4 + eIdx);
        cp_async16(sbase + 2 * BD_ARR * 16u + off, emb_r4 + fIdx);
        cp_async16(sbase + 3 * BD_ARR * 16u + off, emb_i4 + fIdx);
    }
    {
        const float4* Tg = &g_T[pt][0][0];
#pragma unroll
        for (int k = 0; k < 2; k++) {
            int j = t + k * 256;
            cp_async16(tbase + (unsigned)j * 16u, Tg + j);
        }
    }
    asm volatile("cp.async.commit_group;" ::: "memory");
    if (t < 32) s_s[t] = ((const float*)&g_S4[pt][0][0])[t];

    int p  = t & 63;
    int hg = t >> 6;           // 0..3
    int h0 = hg * 2;

#pragma unroll
    for (int stage = 0; stage < 2; stage++) {
        asm volatile("cp.async.wait_group 0;" ::: "memory");
        __syncthreads();

        const float4* Er_s = smem4;
        const float4* Ei_s = Er_s + BD_ARR;
        const float4* Fr_s = Ei_s + BD_ARR;
        const float4* Fi_s = Fr_s + BD_ARR;
        int p0 = stage * 64;

        float2 rP[2], rM[2], iP[2], iM[2];   // per head (merged a/b halves)
#pragma unroll
        for (int hl = 0; hl < 2; hl++) {
            rP[hl] = make_float2(0.f, 0.f); rM[hl] = make_float2(0.f, 0.f);
            iP[hl] = make_float2(0.f, 0.f); iM[hl] = make_float2(0.f, 0.f);
        }

#pragma unroll
        for (int d4 = 0; d4 < 16; d4++) {
            float4 er = Er_s[p * 17 + d4];
            float4 ei = Ei_s[p * 17 + d4];
            float4 fr = Fr_s[p * 17 + d4];
            float4 fi = Fi_s[p * 17 + d4];
            float2 er_a = make_float2(er.x, er.y), er_b = make_float2(er.z, er.w);
            float2 ei_a = make_float2(ei.x, ei.y), ei_b = make_float2(ei.z, ei.w);
            float2 fr_a = make_float2(fr.x, fr.y), fr_b = make_float2(fr.z, fr.w);
            float2 fi_a = make_float2(fi.x, fi.y), fi_b = make_float2(fi.z, fi.w);
#pragma unroll
            for (int hl = 0; hl < 2; hl++) {
                int hv = h0 + hl;
                float4 T1 = T_s[(4 * hv + 0) * 16 + d4];
                float4 T2 = T_s[(4 * hv + 1) * 16 + d4];
                float4 T3 = T_s[(4 * hv + 2) * 16 + d4];
                float4 T4 = T_s[(4 * hv + 3) * 16 + d4];
                float2 T1a = make_float2(T1.x, T1.y), T1b = make_float2(T1.z, T1.w);
                float2 T2a = make_float2(T2.x, T2.y), T2b = make_float2(T2.z, T2.w);
                float2 T3a = make_float2(T3.x, T3.y), T3b = make_float2(T3.z, T3.w);
                float2 T4a = make_float2(T4.x, T4.y), T4b = make_float2(T4.z, T4.w);
                fma2(rP[hl], er_a, T1a);  fma2(rP[hl], er_b, T1b);
                fma2(rM[hl], ei_a, T2a);  fma2(rM[hl], ei_b, T2b);
                fma2(rM[hl], fr_a, T4a);  fma2(rM[hl], fr_b, T4b);
                fma2(rM[hl], fi_a, T3a);  fma2(rM[hl], fi_b, T3b);
                fma2(iP[hl], er_a, T3a);  fma2(iP[hl], er_b, T3b);
                fma2(iP[hl], fr_a, T2a);  fma2(iP[hl], fr_b, T2b);
                fma2(iP[hl], fi_a, T1a);  fma2(iP[hl], fi_b, T1b);
                fma2(iM[hl], ei_a, T4a);  fma2(iM[hl], ei_b, T4b);
            }
        }

#pragma unroll
        for (int hl = 0; hl < 2; hl++) {
            int hv = h0 + hl;
            float r  = (rP[hl].x + rP[hl].y) - (rM[hl].x + rM[hl].y)
                     + s_s[hv * 4 + 0] - s_s[hv * 4 + 1];
            float iv = (iP[hl].x + iP[hl].y) - (iM[hl].x + iM[hl].y)
                     + s_s[hv * 4 + 2] + s_s[hv * 4 + 3];
            g_S2[hv][n][q][b][p0 + p] = sqrtf(r * r + iv * iv);
        }

        if (stage == 0) {
            __syncthreads();   // everyone done reading buffer before refill
#pragma unroll
            for (int k = 0; k < 4; k++) {
                int j  = t + k * 256;
                int pl = j >> 4, d4 = j & 15;
                long eIdx = ((rowE + 64 + pl) * 4 + b) * 16 + d4;
                long fIdx = ((rowF + (long)(64 + pl) * 128) * 4 + b) * 16 + d4;
                unsigned off = (unsigned)(pl * 17 + d4) * 16u;
                cp_async16(sbase + 0 * BD_ARR * 16u + off, emb_r4 + eIdx);
                cp_async16(sbase + 1 * BD_ARR * 16u + off, emb_i4 + eIdx);
                cp_async16(sbase + 2 * BD_ARR * 16u + off, emb_r4 + fIdx);
                cp_async16(sbase + 3 * BD_ARR * 16u + off, emb_i4 + fIdx);
            }
            asm volatile("cp.async.commit_group;" ::: "memory");
        }
    }
}

// ---------------- kernel 5: AC magnitudes, interleaved-k complex GEMM ----------------
// grid (8 = qt(4)*pt(2), B, H*N), block 256: tx(32)->p, ty(8)->4q. Norm folded.
__global__ __launch_bounds__(256) void k_ac(
    const float* __restrict__ ww_r_g, const float* __restrict__ ww_r_bt,
    const float* __restrict__ ww_i_g, const float* __restrict__ ww_i_bt)
{
    int b = blockIdx.y;
    int h = blockIdx.z / N_, n = blockIdx.z % N_;
    int pt = blockIdx.x & 1, qt = blockIdx.x >> 1;
    int q0 = qt * 32, p0 = pt * 64;

    __shared__ float2 kT[64][65];                // [d][p] interleaved (kr,ki)
    __shared__ float  qrT[64][34], qiT[64][34];  // [d][q]
    __shared__ float  Akr[64], Ckr[64], Aki[64], Cki[64];
    __shared__ float  Aqr[64], Cqr[64], Aqi[64], Cqi[64];

    int t = threadIdx.x;
    if (t < 64) {
        int d = t;
        float m0 = g_mean[0][h][n][d], r0s = g_rstd[0][h][n][d];
        float m1 = g_mean[1][h][n][d], r1s = g_rstd[1][h][n][d];
        Akr[d] = r0s;  Ckr[d] = -m0 * r0s;
        Aki[d] = r1s;  Cki[d] = -m1 * r1s;
        float m2 = g_mean[2][h][n][d], r2s = g_rstd[2][h][n][d];
        float m3 = g_mean[3][h][n][d], r3s = g_rstd[3][h][n][d];
        float gr = ww_r_g[h * 64 + d], btr = ww_r_bt[h * 64 + d];
        float gi = ww_i_g[h * 64 + d], bti = ww_i_bt[h * 64 + d];
        Aqr[d] = r2s * gr;  Cqr[d] = btr - m2 * r2s * gr;
        Aqi[d] = r3s * gi;  Cqi[d] = bti - m3 * r3s * gi;
    }
    __syncthreads();

    for (int i = t; i < 64 * 64; i += 256) {
        int p = i >> 6, d = i & 63;
        int row = (n * P_ + p0 + p) * B_ + b;
        float xr = g_wk_r[h][row][d];
        float xi = g_wk_i[h][row][d];
        kT[d][p] = make_float2(xr * Akr[d] + Ckr[d], xi * Aki[d] + Cki[d]);
    }
    for (int i = t; i < 32 * 64; i += 256) {
        int q = i >> 6, d = i & 63;
        int row = (n * Q_ + q0 + q) * B_ + b;
        qrT[d][q] = g_wq_r[h][row][d] * Aqr[d] + Cqr[d];
        qiT[d][q] = g_wq_i[h][row][d] * Aqi[d] + Cqi[d];
    }
    __syncthreads();

    int tx = t & 31, ty = t >> 5;
    int lq0 = ty * 4;

    float2 accR[2][2], accI[2][2];   // [q-pair ii][p j], p_j = tx + 32*j
#pragma unroll
    for (int ii = 0; ii < 2; ii++)
#pragma unroll
        for (int j = 0; j < 2; j++) { accR[ii][j] = make_float2(0.f, 0.f); accI[ii][j] = make_float2(0.f, 0.f); }

#pragma unroll 4
    for (int d = 0; d < 64; d++) {
        float2 kv0 = kT[d][tx];
        float2 kv1 = kT[d][tx + 32];
        float2 qr20 = *(const float2*)&qrT[d][lq0];
        float2 qr21 = *(const float2*)&qrT[d][lq0 + 2];
        float2 qi20 = *(const float2*)&qiT[d][lq0];
        float2 qi21 = *(const float2*)&qiT[d][lq0 + 2];
        float2 nqi20 = neg2(qi20), nqi21 = neg2(qi21);
        {
            float2 kr2 = dup2(kv0.x), ki2 = dup2(kv0.y);
            fma2(accR[0][0], qr20, kr2);  fma2(accR[0][0], nqi20, ki2);
            fma2(accI[0][0], qr20, ki2);  fma2(accI[0][0], qi20,  kr2);
            fma2(accR[1][0], qr21, kr2);  fma2(accR[1][0], nqi21, ki2);
            fma2(accI[1][0], qr21, ki2);  fma2(accI[1][0], qi21,  kr2);
        }
        {
            float2 kr2 = dup2(kv1.x), ki2 = dup2(kv1.y);
            fma2(accR[0][1], qr20, kr2);  fma2(accR[0][1], nqi20, ki2);
            fma2(accI[0][1], qr20, ki2);  fma2(accI[0][1], qi20,  kr2);
            fma2(accR[1][1], qr21, kr2);  fma2(accR[1][1], nqi21, ki2);
            fma2(accI[1][1], qr21, ki2);  fma2(accI[1][1], qi21,  kr2);
        }
    }

#pragma unroll
    for (int ii = 0; ii < 2; ii++)
#pragma unroll
        for (int j = 0; j < 2; j++) {
            int qg = q0 + lq0 + 2 * ii;
            int p  = p0 + tx + 32 * j;
            float r0v = accR[ii][j].x, i0v = accI[ii][j].x;
            float r1v = accR[ii][j].y, i1v = accI[ii][j].y;
            g_S[h][n][qg][b][p]     = sqrtf(r0v * r0v + i0v * i0v);
            g_S[h][n][qg + 1][b][p] = sqrtf(r1v * r1v + i1v * i1v);
        }
}

// ---------------- kernel 6: softmax over b (sums AC + BD) ----------------
__global__ __launch_bounds__(256) void k_softmax()
{
    int idx = blockIdx.x * 256 + threadIdx.x;
    int p  = idx % P_;
    int q  = (idx / P_) % Q_;
    int hn = idx / (P_ * Q_);
    size_t off = (((size_t)hn * Q_ + q) * B_) * P_ + p;
    float* baseA = &g_S[0][0][0][0][0] + off;
    const float* baseB = &g_S2[0][0][0][0][0] + off;
    float v0 = (baseA[0 * P_] + baseB[0 * P_]) * TEMPF;
    float v1 = (baseA[1 * P_] + baseB[1 * P_]) * TEMPF;
    float v2 = (baseA[2 * P_] + baseB[2 * P_]) * TEMPF;
    float v3 = (baseA[3 * P_] + baseB[3 * P_]) * TEMPF;
    float m = fmaxf(fmaxf(v0, v1), fmaxf(v2, v3));
    v0 = __expf(v0 - m); v1 = __expf(v1 - m); v2 = __expf(v2 - m); v3 = __expf(v3 - m);
    float inv = 1.f / (v0 + v1 + v2 + v3);
    baseA[0 * P_] = v0 * inv;
    baseA[1 * P_] = v1 * inv;
    baseA[2 * P_] = v2 * inv;
    baseA[3 * P_] = v3 * inv;
}

// ---------------- kernel 7: output aggregation (GEMM per (h,n,b,q-tile)) ----------------
// grid (4 q-tiles of 32, B, H*N), block 256: tx(16)->4d, ty(16)->2q
__global__ __launch_bounds__(256) void k_out(
    const float* __restrict__ vr, const float* __restrict__ vi,
    float* __restrict__ out)
{
    int b = blockIdx.y;
    int h = blockIdx.z / N_, n = blockIdx.z % N_;
    int q0 = blockIdx.x * 32;

    __shared__ float aff_s[32][64];          // [q][p-chunk]
    __shared__ float vr_s[64][D_], vi_s[64][D_];

    int t = threadIdx.x;
    int tx = t & 15, ty = t >> 4;
    int d0 = tx * 4, lq0 = ty * 2;

    float2 cr[2][2], ci[2][2];
#pragma unroll
    for (int i = 0; i < 2; i++)
#pragma unroll
        for (int j = 0; j < 2; j++) { cr[i][j] = make_float2(0.f, 0.f); ci[i][j] = make_float2(0.f, 0.f); }

    for (int c = 0; c < 2; c++) {
        __syncthreads();
        int p0 = c * 64;
        for (int i = t; i < 32 * 64; i += 256) {
            int lq = i >> 6, pp = i & 63;
            aff_s[lq][pp] = g_S[h][n][q0 + lq][b][p0 + pp];
        }
        for (int i = t; i < 64 * D_; i += 256) {
            int pp = i >> 6, d = i & 63;
            size_t off = (((size_t)n * P_ + p0 + pp) * B_ + b) * D_ + d;
            vr_s[pp][d] = vr[off];
            vi_s[pp][d] = vi[off];
        }
        __syncthreads();

#pragma unroll 4
        for (int pp = 0; pp < 64; pp++) {
            float2 v_r0 = *(const float2*)&vr_s[pp][d0];
            float2 v_r1 = *(const float2*)&vr_s[pp][d0 + 2];
            float2 v_i0 = *(const float2*)&vi_s[pp][d0];
            float2 v_i1 = *(const float2*)&vi_s[pp][d0 + 2];
#pragma unroll
            for (int i = 0; i < 2; i++) {
                float2 a2 = dup2(aff_s[lq0 + i][pp]);
                fma2(cr[i][0], a2, v_r0);  fma2(cr[i][1], a2, v_r1);
                fma2(ci[i][0], a2, v_i0);  fma2(ci[i][1], a2, v_i1);
            }
        }
    }

#pragma unroll
    for (int i = 0; i < 2; i++) {
        int qg = q0 + lq0 + i;
        size_t o = (((size_t)n * Q_ + qg) * B_ + b) * (H_ * D_) + h * D_ + d0;
        *(float2*)(out + o)     = cr[i][0];
        *(float2*)(out + o + 2) = cr[i][1];
        size_t oi = o + (size_t)N_ * Q_ * B_ * H_ * D_;
        *(float2*)(out + oi)     = ci[i][0];
        *(float2*)(out + oi + 2) = ci[i][1];
    }
}

// ---------------- launch ----------------
extern "C" void kernel_launch(void* const* d_in, const int* in_sizes, int n_in,
                              void* d_out, int out_size)
{
    const float* query_r = (const float*)d_in[0];
    const float* query_i = (const float*)d_in[1];
    const float* key_r   = (const float*)d_in[2];
    const float* key_i   = (const float*)d_in[3];
    const float* val_r   = (const float*)d_in[4];
    const float* val_i   = (const float*)d_in[5];
    const float* emb_r   = (const float*)d_in[6];
    const float* emb_i   = (const float*)d_in[7];
    const float* WKr_w   = (const float*)d_in[8];
    const float* WKr_b   = (const float*)d_in[9];
    const float* WKi_w   = (const float*)d_in[10];
    const float* WKi_b   = (const float*)d_in[11];
    const float* WKRr_w  = (const float*)d_in[12];
    const float* WKRr_b  = (const float*)d_in[13];
    const float* WKRi_w  = (const float*)d_in[14];
    const float* WKRi_b  = (const float*)d_in[15];
    const float* WQr_w   = (const float*)d_in[16];
    const float* WQr_b   = (const float*)d_in[17];
    const float* WQi_w   = (const float*)d_in[18];
    const float* WQi_b   = (const float*)d_in[19];
    const float* ww_r_g  = (const float*)d_in[20];
    const float* ww_r_bt = (const float*)d_in[21];
    const float* ww_i_g  = (const float*)d_in[22];
    const float* ww_i_bt = (const float*)d_in[23];
    const float* wr_r_g  = (const float*)d_in[24];
    const float* wr_r_bt = (const float*)d_in[25];
    const float* wr_i_g  = (const float*)d_in[26];
    const float* wr_i_bt = (const float*)d_in[27];

    cudaFuncSetAttribute(k_bd, cudaFuncAttributeMaxDynamicSharedMemorySize, SMEM_BD);

    k_proj<<<dim3(32, H_, 2), 256>>>(key_r, key_i, query_r, query_i,
                                     WKr_w, WKr_b, WKi_w, WKi_b,
                                     WQr_w, WQr_b, WQi_w, WQi_b);
    k_stats<<<dim3(N_, H_, 4), 512>>>();
    k_tvec<<<dim3(32, H_), 256>>>(WKRr_w, WKRr_b, WKRi_w, WKRi_b,
                                  wr_r_g, wr_r_bt, wr_i_g, wr_i_bt);
    k_bd<<<ROWS_, 256, SMEM_BD>>>((const float4*)emb_r, (const float4*)emb_i);
    k_ac<<<dim3(8, B_, H_ * N_), 256>>>(ww_r_g, ww_r_bt, ww_i_g, ww_i_bt);
    k_softmax<<<1024, 256>>>();
    k_out<<<dim3(4, B_, H_ * N_), 256>>>(val_r, val_i, (float*)d_out);
}

// round 10
// speedup vs baseline: 1.0900x; 1.0190x over previous
#include <cuda_runtime.h>
#include <math.h>

#define H_ 8
#define D_ 64
#define N_ 2
#define Q_ 128
#define P_ 128
#define B_ 4
#define ROWS_ 1024          // N_*Q_*B_ == N_*P_*B_
#define EPSF 1e-5f
#define TEMPF 30.0f

// k_bd dynamic smem: ONE stage buffer (4 arrays x [64][17] float4) + T[512] float4 + 32 floats
#define BD_ARR   (64 * 17)
#define BD_STAGE (4 * BD_ARR)
#define SMEM_BD  ((BD_STAGE + 512) * 16 + 128)

// k_proj smem: W 2x[64][68] + X 2x[64][64]  (floats)
#define PROJ_W   (64 * 68)
#define PROJ_X   (64 * 64)
#define SMEM_PROJ ((2 * PROJ_W + 2 * PROJ_X) * 4)
// k_tvec smem: W 2x[64][68] + U 2x[32][64] + bm/bp 2x64 + A/C 4x64
#define TVEC_W   (64 * 68)
#define TVEC_U   (32 * 64)
#define SMEM_TVEC ((2 * TVEC_W + 2 * TVEC_U + 2 * 64 + 4 * 64) * 4)
// k_ac smem: kr/ki [64][132] + qr/qi [64][36] + A/C 8x64
#define AC_K     (64 * 132)
#define AC_Q     (64 * 36)
#define SMEM_AC  ((2 * AC_K + 2 * AC_Q + 8 * 64) * 4)
// k_out smem: aff[64][64] + vr[64][64] + vi[64][64]
#define SMEM_OUT (3 * 64 * 64 * 4)

// ---------------- packed fp32x2 FMA (sm_103a FFMA2) ----------------
__device__ __forceinline__ void fma2(float2& d, float2 a, float2 b) {
    asm("fma.rn.f32x2 %0, %1, %2, %0;"
        : "+l"(reinterpret_cast<unsigned long long&>(d))
        : "l"(reinterpret_cast<unsigned long long&>(a)),
          "l"(reinterpret_cast<unsigned long long&>(b)));
}
__device__ __forceinline__ float2 dup2(float v) { return make_float2(v, v); }

__device__ __forceinline__ void cp_async16(unsigned dst_smem, const void* src) {
    asm volatile("cp.async.cg.shared.global [%0], [%1], 16;" :: "r"(dst_smem), "l"(src));
}

// ---------------- scratch (device globals; no allocation) ----------------
__device__ float  g_wk_r[H_][ROWS_][D_];   // RAW projections (pre-norm)
__device__ float  g_wk_i[H_][ROWS_][D_];
__device__ float  g_wq_r[H_][ROWS_][D_];
__device__ float  g_wq_i[H_][ROWS_][D_];
__device__ float  g_mean[4][H_][N_][64];
__device__ float  g_rstd[4][H_][N_][64];
__device__ float4 g_T [ROWS_][32][16];
__device__ float  g_S4[ROWS_][H_][4];
__device__ float  g_S [H_][N_][Q_][B_][P_];
__device__ float  g_S2[H_][N_][Q_][B_][P_];

// ---------------- kernel 1: complex projections, 4row x 8d tiles ----------------
// grid (16 row-tiles of 64, H, 2), block 128: tx(8)->8d, ty(16)->4rows
__global__ __launch_bounds__(128) void k_proj(
    const float* __restrict__ kr, const float* __restrict__ ki,
    const float* __restrict__ qr, const float* __restrict__ qi,
    const float* __restrict__ WKr, const float* __restrict__ WKrb,
    const float* __restrict__ WKi, const float* __restrict__ WKib,
    const float* __restrict__ WQr, const float* __restrict__ WQrb,
    const float* __restrict__ WQi, const float* __restrict__ WQib)
{
    int h   = blockIdx.y;
    int isQ = blockIdx.z;
    const float* xr = isQ ? qr : kr;
    const float* xi = isQ ? qi : ki;
    const float* Wr = (isQ ? WQr : WKr) + h * D_ * D_;
    const float* Wi = (isQ ? WQi : WKi) + h * D_ * D_;
    const float* br = (isQ ? WQrb : WKrb) + h * D_;
    const float* bi = (isQ ? WQib : WKib) + h * D_;
    float* outR = isQ ? &g_wq_r[h][0][0] : &g_wk_r[h][0][0];
    float* outI = isQ ? &g_wq_i[h][0][0] : &g_wk_i[h][0][0];

    extern __shared__ float sm_p[];
    float* Wr_t = sm_p;                    // [e][d] pad 68
    float* Wi_t = Wr_t + PROJ_W;
    float* Xr   = Wi_t + PROJ_W;           // [row][e] 64x64
    float* Xi   = Xr + PROJ_X;

    int t = threadIdx.x;
    for (int i = t; i < D_ * D_; i += 128) {
        int d = i >> 6, e = i & 63;
        Wr_t[e * 68 + d] = Wr[i];
        Wi_t[e * 68 + d] = Wi[i];
    }
    int row0 = blockIdx.x * 64;
    const float4* xr4 = (const float4*)(xr + (size_t)row0 * D_);
    const float4* xi4 = (const float4*)(xi + (size_t)row0 * D_);
    for (int i = t; i < 64 * 16; i += 128) {
        ((float4*)Xr)[i] = xr4[i];
        ((float4*)Xi)[i] = xi4[i];
    }
    __syncthreads();

    int tx = t & 7, ty = t >> 3;
    int d0 = tx * 8, r0 = ty * 4;

    float2 ar[4][4], ai[4][4];
#pragma unroll
    for (int i = 0; i < 4; i++)
#pragma unroll
        for (int j = 0; j < 4; j++) { ar[i][j] = make_float2(0.f, 0.f); ai[i][j] = make_float2(0.f, 0.f); }

#pragma unroll 2
    for (int e = 0; e < 64; e++) {
        float4 w0 = *(const float4*)&Wr_t[e * 68 + d0];
        float4 w1 = *(const float4*)&Wr_t[e * 68 + d0 + 4];
        float4 v0 = *(const float4*)&Wi_t[e * 68 + d0];
        float4 v1 = *(const float4*)&Wi_t[e * 68 + d0 + 4];
        float2 wrp[4] = { make_float2(w0.x, w0.y), make_float2(w0.z, w0.w),
                          make_float2(w1.x, w1.y), make_float2(w1.z, w1.w) };
        float2 wip[4] = { make_float2(v0.x, v0.y), make_float2(v0.z, v0.w),
                          make_float2(v1.x, v1.y), make_float2(v1.z, v1.w) };
#pragma unroll
        for (int i = 0; i < 4; i++) {
            float vr = Xr[(r0 + i) * 64 + e];
            float vi = Xi[(r0 + i) * 64 + e];
            float2 vr2 = dup2(vr), vi2 = dup2(vi), nvi2 = dup2(-vi);
#pragma unroll
            for (int j = 0; j < 4; j++) {
                fma2(ar[i][j], vr2, wrp[j]);  fma2(ar[i][j], nvi2, wip[j]);
                fma2(ai[i][j], vr2, wip[j]);  fma2(ai[i][j], vi2,  wrp[j]);
            }
        }
    }

    float4 bR0 = *(const float4*)&br[d0];
    float4 bR1 = *(const float4*)&br[d0 + 4];
    float4 bI0 = *(const float4*)&bi[d0];
    float4 bI1 = *(const float4*)&bi[d0 + 4];
    float bRs[8] = { bR0.x, bR0.y, bR0.z, bR0.w, bR1.x, bR1.y, bR1.z, bR1.w };
    float bIs[8] = { bI0.x, bI0.y, bI0.z, bI0.w, bI1.x, bI1.y, bI1.z, bI1.w };
#pragma unroll
    for (int i = 0; i < 4; i++) {
#pragma unroll
        for (int j = 0; j < 4; j++) {
            ar[i][j].x += bRs[2 * j]     - bIs[2 * j];
            ar[i][j].y += bRs[2 * j + 1] - bIs[2 * j + 1];
            ai[i][j].x += bRs[2 * j]     + bIs[2 * j];
            ai[i][j].y += bRs[2 * j + 1] + bIs[2 * j + 1];
        }
        float* oR = outR + (size_t)(row0 + r0 + i) * D_ + d0;
        float* oI = outI + (size_t)(row0 + r0 + i) * D_ + d0;
        *(float4*)(oR)     = make_float4(ar[i][0].x, ar[i][0].y, ar[i][1].x, ar[i][1].y);
        *(float4*)(oR + 4) = make_float4(ar[i][2].x, ar[i][2].y, ar[i][3].x, ar[i][3].y);
        *(float4*)(oI)     = make_float4(ai[i][0].x, ai[i][0].y, ai[i][1].x, ai[i][1].y);
        *(float4*)(oI + 4) = make_float4(ai[i][2].x, ai[i][2].y, ai[i][3].x, ai[i][3].y);
    }
}

// ---------------- kernel 2: instance-norm STATS only ----------------
__global__ __launch_bounds__(512) void k_stats()
{
    int n = blockIdx.x, h = blockIdx.y, a = blockIdx.z;
    const float* base;
    if      (a == 0) base = &g_wk_r[0][0][0];
    else if (a == 1) base = &g_wk_i[0][0][0];
    else if (a == 2) base = &g_wq_r[0][0][0];
    else             base = &g_wq_i[0][0][0];
    const float* x = base + ((size_t)h * ROWS_ + (size_t)n * 512) * D_;

    int t = threadIdx.x;
    int d = t & 63, c = t >> 6;
    float s = 0.f, s2 = 0.f;
    for (int r = c * 64; r < (c + 1) * 64; r++) {
        float v = x[r * 64 + d];
        s += v; s2 += v * v;
    }
    __shared__ float Ss[8][64], S2s[8][64];
    Ss[c][d] = s; S2s[c][d] = s2;
    __syncthreads();
    if (t < 64) {
        float sum = 0.f, sum2 = 0.f;
#pragma unroll
        for (int cc = 0; cc < 8; cc++) { sum += Ss[cc][t]; sum2 += S2s[cc][t]; }
        float m   = sum * (1.f / 512.f);
        float var = sum2 * (1.f / 512.f) - m * m;
        g_mean[a][h][n][t] = m;
        g_rstd[a][h][n][t] = rsqrtf(var + EPSF);
    }
}

// ---------------- kernel 3: t-vectors, 2row x 8e tiles ----------------
// grid (32 tiles of 32 rows, H), block 128: tx(8)->8e, ty(16)->2rows
__global__ __launch_bounds__(128) void k_tvec(
    const float* __restrict__ WKRr, const float* __restrict__ WKRrb,
    const float* __restrict__ WKRi, const float* __restrict__ WKRib,
    const float* __restrict__ wr_r_g, const float* __restrict__ wr_r_bt,
    const float* __restrict__ wr_i_g, const float* __restrict__ wr_i_bt)
{
    int h = blockIdx.y;
    int pt0 = blockIdx.x * 32;
    int n = pt0 >> 9;

    extern __shared__ float sm_t[];
    float* Wr_s = sm_t;                   // [d][e] pad 68
    float* Wi_s = Wr_s + TVEC_W;
    float* Ur   = Wi_s + TVEC_W;          // [32][64]
    float* Ui   = Ur + TVEC_U;
    float* bm_s = Ui + TVEC_U;            // [64]
    float* bp_s = bm_s + 64;
    float* Ar_s = bp_s + 64;
    float* Cr_s = Ar_s + 64;
    float* Ai_s = Cr_s + 64;
    float* Ci_s = Ai_s + 64;

    int t = threadIdx.x;
    const float* Wr = WKRr + h * D_ * D_;
    const float* Wi = WKRi + h * D_ * D_;
    for (int i = t; i < D_ * D_; i += 128) {
        int dd = i >> 6, e = i & 63;
        Wr_s[dd * 68 + e] = Wr[i];
        Wi_s[dd * 68 + e] = Wi[i];
    }
    if (t < 64) {
        float brv = WKRrb[h * D_ + t], biv = WKRib[h * D_ + t];
        bm_s[t] = brv - biv;
        bp_s[t] = brv + biv;
        float m2 = g_mean[2][h][n][t], r2 = g_rstd[2][h][n][t];
        float m3 = g_mean[3][h][n][t], r3 = g_rstd[3][h][n][t];
        float gr = wr_r_g[h * 64 + t], btr = wr_r_bt[h * 64 + t];
        float gi = wr_i_g[h * 64 + t], bti = wr_i_bt[h * 64 + t];
        Ar_s[t] = r2 * gr;  Cr_s[t] = btr - m2 * r2 * gr;
        Ai_s[t] = r3 * gi;  Ci_s[t] = bti - m3 * r3 * gi;
    }
    __syncthreads();
    for (int i = t; i < 32 * D_; i += 128) {
        int l = i >> 6, d = i & 63;
        Ur[l * 64 + d] = g_wq_r[h][pt0 + l][d] * Ar_s[d] + Cr_s[d];
        Ui[l * 64 + d] = g_wq_i[h][pt0 + l][d] * Ai_s[d] + Ci_s[d];
    }
    __syncthreads();

    int tx = t & 7, ty = t >> 3;
    int e0 = tx * 8, r0 = ty * 2;

    float2 t1[2][4], t2[2][4], t3[2][4], t4[2][4];
#pragma unroll
    for (int i = 0; i < 2; i++)
#pragma unroll
        for (int j = 0; j < 4; j++) {
            t1[i][j] = make_float2(0.f, 0.f); t2[i][j] = make_float2(0.f, 0.f);
            t3[i][j] = make_float2(0.f, 0.f); t4[i][j] = make_float2(0.f, 0.f);
        }

#pragma unroll 2
    for (int dd = 0; dd < 64; dd++) {
        float4 w0 = *(const float4*)&Wr_s[dd * 68 + e0];
        float4 w1 = *(const float4*)&Wr_s[dd * 68 + e0 + 4];
        float4 v0 = *(const float4*)&Wi_s[dd * 68 + e0];
        float4 v1 = *(const float4*)&Wi_s[dd * 68 + e0 + 4];
        float2 wrp[4] = { make_float2(w0.x, w0.y), make_float2(w0.z, w0.w),
                          make_float2(w1.x, w1.y), make_float2(w1.z, w1.w) };
        float2 wip[4] = { make_float2(v0.x, v0.y), make_float2(v0.z, v0.w),
                          make_float2(v1.x, v1.y), make_float2(v1.z, v1.w) };
#pragma unroll
        for (int i = 0; i < 2; i++) {
            float2 u2r = dup2(Ur[(r0 + i) * 64 + dd]);
            float2 u2i = dup2(Ui[(r0 + i) * 64 + dd]);
#pragma unroll
            for (int j = 0; j < 4; j++) {
                fma2(t1[i][j], u2r, wrp[j]);
                fma2(t2[i][j], u2r, wip[j]);
                fma2(t3[i][j], u2i, wrp[j]);
                fma2(t4[i][j], u2i, wip[j]);
            }
        }
    }

#pragma unroll
    for (int i = 0; i < 2; i++) {
        float* base = (float*)&g_T[pt0 + r0 + i][h * 4][0];
        *(float4*)(base +   0 + e0)     = make_float4(t1[i][0].x, t1[i][0].y, t1[i][1].x, t1[i][1].y);
        *(float4*)(base +   0 + e0 + 4) = make_float4(t1[i][2].x, t1[i][2].y, t1[i][3].x, t1[i][3].y);
        *(float4*)(base +  64 + e0)     = make_float4(t2[i][0].x, t2[i][0].y, t2[i][1].x, t2[i][1].y);
        *(float4*)(base +  64 + e0 + 4) = make_float4(t2[i][2].x, t2[i][2].y, t2[i][3].x, t2[i][3].y);
        *(float4*)(base + 128 + e0)     = make_float4(t3[i][0].x, t3[i][0].y, t3[i][1].x, t3[i][1].y);
        *(float4*)(base + 128 + e0 + 4) = make_float4(t3[i][2].x, t3[i][2].y, t3[i][3].x, t3[i][3].y);
        *(float4*)(base + 192 + e0)     = make_float4(t4[i][0].x, t4[i][0].y, t4[i][1].x, t4[i][1].y);
        *(float4*)(base + 192 + e0 + 4) = make_float4(t4[i][2].x, t4[i][2].y, t4[i][3].x, t4[i][3].y);
    }

    if (tx == 0) {
#pragma unroll
        for (int i = 0; i < 2; i++) {
            float s1 = 0.f, s2v = 0.f, s3 = 0.f, s4 = 0.f;
            for (int dd = 0; dd < 64; dd++) {
                float u_r = Ur[(r0 + i) * 64 + dd], u_i = Ui[(r0 + i) * 64 + dd];
                float bm = bm_s[dd], bp = bp_s[dd];
                s1 += bm * u_r;  s2v += bp * u_i;
                s3 += bm * u_i;  s4 += bp * u_r;
            }
            int pt = pt0 + r0 + i;
            g_S4[pt][h][0] = s1;  g_S4[pt][h][1] = s2v;
            g_S4[pt][h][2] = s3;  g_S4[pt][h][3] = s4;
        }
    }
}

// ---------------- kernel 4: BD (unchanged from R9) ----------------
__global__ __launch_bounds__(256) void k_bd(
    const float4* __restrict__ emb_r4, const float4* __restrict__ emb_i4)
{
    int pt = blockIdx.x;
    int b  = pt & 3;
    int q  = (pt >> 2) & 127;
    int n  = pt >> 9;

    extern __shared__ float4 smem4[];
    float4* T_s = smem4 + BD_STAGE;
    float*  s_s = (float*)(T_s + 512);

    int t = threadIdx.x;
    unsigned sbase = (unsigned)__cvta_generic_to_shared(smem4);
    unsigned tbase = (unsigned)__cvta_generic_to_shared(T_s);

    long rowE = ((long)n * 128 + q) * 128;
    long rowF = ((long)n * 128) * 128 + q;

#pragma unroll
    for (int k = 0; k < 4; k++) {
        int j  = t + k * 256;
        int pl = j >> 4, d4 = j & 15;
        long eIdx = ((rowE + pl) * 4 + b) * 16 + d4;
        long fIdx = ((rowF + (long)pl * 128) * 4 + b) * 16 + d4;
        unsigned off = (unsigned)(pl * 17 + d4) * 16u;
        cp_async16(sbase + 0 * BD_ARR * 16u + off, emb_r4 + eIdx);
        cp_async16(sbase + 1 * BD_ARR * 16u + off, emb_i4 + eIdx);
        cp_async16(sbase + 2 * BD_ARR * 16u + off, emb_r4 + fIdx);
        cp_async16(sbase + 3 * BD_ARR * 16u + off, emb_i4 + fIdx);
    }
    {
        const float4* Tg = &g_T[pt][0][0];
#pragma unroll
        for (int k = 0; k < 2; k++) {
            int j = t + k * 256;
            cp_async16(tbase + (unsigned)j * 16u, Tg + j);
        }
    }
    asm volatile("cp.async.commit_group;" ::: "memory");
    if (t < 32) s_s[t] = ((const float*)&g_S4[pt][0][0])[t];

    int p  = t & 63;
    int hg = t >> 6;
    int h0 = hg * 2;

#pragma unroll
    for (int stage = 0; stage < 2; stage++) {
        asm volatile("cp.async.wait_group 0;" ::: "memory");
        __syncthreads();

        const float4* Er_s = smem4;
        const float4* Ei_s = Er_s + BD_ARR;
        const float4* Fr_s = Ei_s + BD_ARR;
        const float4* Fi_s = Fr_s + BD_ARR;
        int p0 = stage * 64;

        float2 rP[2], rM[2], iP[2], iM[2];
#pragma unroll
        for (int hl = 0; hl < 2; hl++) {
            rP[hl] = make_float2(0.f, 0.f); rM[hl] = make_float2(0.f, 0.f);
            iP[hl] = make_float2(0.f, 0.f); iM[hl] = make_float2(0.f, 0.f);
        }

#pragma unroll
        for (int d4 = 0; d4 < 16; d4++) {
            float4 er = Er_s[p * 17 + d4];
            float4 ei = Ei_s[p * 17 + d4];
            float4 fr = Fr_s[p * 17 + d4];
            float4 fi = Fi_s[p * 17 + d4];
            float2 er_a = make_float2(er.x, er.y), er_b = make_float2(er.z, er.w);
            float2 ei_a = make_float2(ei.x, ei.y), ei_b = make_float2(ei.z, ei.w);
            float2 fr_a = make_float2(fr.x, fr.y), fr_b = make_float2(fr.z, fr.w);
            float2 fi_a = make_float2(fi.x, fi.y), fi_b = make_float2(fi.z, fi.w);
#pragma unroll
            for (int hl = 0; hl < 2; hl++) {
                int hv = h0 + hl;
                float4 T1 = T_s[(4 * hv + 0) * 16 + d4];
                float4 T2 = T_s[(4 * hv + 1) * 16 + d4];
                float4 T3 = T_s[(4 * hv + 2) * 16 + d4];
                float4 T4 = T_s[(4 * hv + 3) * 16 + d4];
                float2 T1a = make_float2(T1.x, T1.y), T1b = make_float2(T1.z, T1.w);
                float2 T2a = make_float2(T2.x, T2.y), T2b = make_float2(T2.z, T2.w);
                float2 T3a = make_float2(T3.x, T3.y), T3b = make_float2(T3.z, T3.w);
                float2 T4a = make_float2(T4.x, T4.y), T4b = make_float2(T4.z, T4.w);
                fma2(rP[hl], er_a, T1a);  fma2(rP[hl], er_b, T1b);
                fma2(rM[hl], ei_a, T2a);  fma2(rM[hl], ei_b, T2b);
                fma2(rM[hl], fr_a, T4a);  fma2(rM[hl], fr_b, T4b);
                fma2(rM[hl], fi_a, T3a);  fma2(rM[hl], fi_b, T3b);
                fma2(iP[hl], er_a, T3a);  fma2(iP[hl], er_b, T3b);
                fma2(iP[hl], fr_a, T2a);  fma2(iP[hl], fr_b, T2b);
                fma2(iP[hl], fi_a, T1a);  fma2(iP[hl], fi_b, T1b);
                fma2(iM[hl], ei_a, T4a);  fma2(iM[hl], ei_b, T4b);
            }
        }

#pragma unroll
        for (int hl = 0; hl < 2; hl++) {
            int hv = h0 + hl;
            float r  = (rP[hl].x + rP[hl].y) - (rM[hl].x + rM[hl].y)
                     + s_s[hv * 4 + 0] - s_s[hv * 4 + 1];
            float iv = (iP[hl].x + iP[hl].y) - (iM[hl].x + iM[hl].y)
                     + s_s[hv * 4 + 2] + s_s[hv * 4 + 3];
            g_S2[hv][n][q][b][p0 + p] = sqrtf(r * r + iv * iv);
        }

        if (stage == 0) {
            __syncthreads();
#pragma unroll
            for (int k = 0; k < 4; k++) {
                int j  = t + k * 256;
                int pl = j >> 4, d4 = j & 15;
                long eIdx = ((rowE + 64 + pl) * 4 + b) * 16 + d4;
                long fIdx = ((rowF + (long)(64 + pl) * 128) * 4 + b) * 16 + d4;
                unsigned off = (unsigned)(pl * 17 + d4) * 16u;
                cp_async16(sbase + 0 * BD_ARR * 16u + off, emb_r4 + eIdx);
                cp_async16(sbase + 1 * BD_ARR * 16u + off, emb_i4 + eIdx);
                cp_async16(sbase + 2 * BD_ARR * 16u + off, emb_r4 + fIdx);
                cp_async16(sbase + 3 * BD_ARR * 16u + off, emb_i4 + fIdx);
            }
            asm volatile("cp.async.commit_group;" ::: "memory");
        }
    }
}

// ---------------- kernel 5: AC, 4q x 4p tiles, separated kr/ki planes ----------------
// grid (4 q-tiles of 32, B, H*N), block 256: tx(32)->4p (full 128 p), ty(8)->4q
__global__ __launch_bounds__(256) void k_ac(
    const float* __restrict__ ww_r_g, const float* __restrict__ ww_r_bt,
    const float* __restrict__ ww_i_g, const float* __restrict__ ww_i_bt)
{
    int b = blockIdx.y;
    int h = blockIdx.z / N_, n = blockIdx.z % N_;
    int q0 = blockIdx.x * 32;

    extern __shared__ float sm_a[];
    float* krT = sm_a;                    // [d][p] pad 132
    float* kiT = krT + AC_K;
    float* qrT = kiT + AC_K;              // [d][q] pad 36
    float* qiT = qrT + AC_Q;
    float* Akr = qiT + AC_Q;  float* Ckr = Akr + 64;
    float* Aki = Ckr + 64;    float* Cki = Aki + 64;
    float* Aqr = Cki + 64;    float* Cqr = Aqr + 64;
    float* Aqi = Cqr + 64;    float* Cqi = Aqi + 64;

    int t = threadIdx.x;
    if (t < 64) {
        int d = t;
        float m0 = g_mean[0][h][n][d], r0s = g_rstd[0][h][n][d];
        float m1 = g_mean[1][h][n][d], r1s = g_rstd[1][h][n][d];
        Akr[d] = r0s;  Ckr[d] = -m0 * r0s;
        Aki[d] = r1s;  Cki[d] = -m1 * r1s;
        float m2 = g_mean[2][h][n][d], r2s = g_rstd[2][h][n][d];
        float m3 = g_mean[3][h][n][d], r3s = g_rstd[3][h][n][d];
        float gr = ww_r_g[h * 64 + d], btr = ww_r_bt[h * 64 + d];
        float gi = ww_i_g[h * 64 + d], bti = ww_i_bt[h * 64 + d];
        Aqr[d] = r2s * gr;  Cqr[d] = btr - m2 * r2s * gr;
        Aqi[d] = r3s * gi;  Cqi[d] = bti - m3 * r3s * gi;
    }
    __syncthreads();

    for (int i = t; i < 128 * 64; i += 256) {
        int p = i >> 6, d = i & 63;
        int row = (n * P_ + p) * B_ + b;
        krT[d * 132 + p] = g_wk_r[h][row][d] * Akr[d] + Ckr[d];
        kiT[d * 132 + p] = g_wk_i[h][row][d] * Aki[d] + Cki[d];
    }
    for (int i = t; i < 32 * 64; i += 256) {
        int q = i >> 6, d = i & 63;
        int row = (n * Q_ + q0 + q) * B_ + b;
        qrT[d * 36 + q] = g_wq_r[h][row][d] * Aqr[d] + Cqr[d];
        qiT[d * 36 + q] = g_wq_i[h][row][d] * Aqi[d] + Cqi[d];
    }
    __syncthreads();

    int tx = t & 31, ty = t >> 5;
    int lq0 = ty * 4, pp0 = tx * 4;

    float2 accR[4][2], accI[4][2];   // [q][ppair]
#pragma unroll
    for (int qq = 0; qq < 4; qq++)
#pragma unroll
        for (int j = 0; j < 2; j++) { accR[qq][j] = make_float2(0.f, 0.f); accI[qq][j] = make_float2(0.f, 0.f); }

#pragma unroll 4
    for (int d = 0; d < 64; d++) {
        float4 kr4 = *(const float4*)&krT[d * 132 + pp0];
        float4 ki4 = *(const float4*)&kiT[d * 132 + pp0];
        float2 krp[2] = { make_float2(kr4.x, kr4.y), make_float2(kr4.z, kr4.w) };
        float2 kip[2] = { make_float2(ki4.x, ki4.y), make_float2(ki4.z, ki4.w) };
        float4 qr4 = *(const float4*)&qrT[d * 36 + lq0];
        float4 qi4 = *(const float4*)&qiT[d * 36 + lq0];
        float qrs[4] = { qr4.x, qr4.y, qr4.z, qr4.w };
        float qis[4] = { qi4.x, qi4.y, qi4.z, qi4.w };
#pragma unroll
        for (int qq = 0; qq < 4; qq++) {
            float2 qr2  = dup2(qrs[qq]);
            float2 qi2  = dup2(qis[qq]);
            float2 nqi2 = dup2(-qis[qq]);
#pragma unroll
            for (int j = 0; j < 2; j++) {
                fma2(accR[qq][j], qr2,  krp[j]);  fma2(accR[qq][j], nqi2, kip[j]);
                fma2(accI[qq][j], qr2,  kip[j]);  fma2(accI[qq][j], qi2,  krp[j]);
            }
        }
    }

#pragma unroll
    for (int qq = 0; qq < 4; qq++) {
        float4 mag;
        mag.x = sqrtf(accR[qq][0].x * accR[qq][0].x + accI[qq][0].x * accI[qq][0].x);
        mag.y = sqrtf(accR[qq][0].y * accR[qq][0].y + accI[qq][0].y * accI[qq][0].y);
        mag.z = sqrtf(accR[qq][1].x * accR[qq][1].x + accI[qq][1].x * accI[qq][1].x);
        mag.w = sqrtf(accR[qq][1].y * accR[qq][1].y + accI[qq][1].y * accI[qq][1].y);
        *(float4*)&g_S[h][n][q0 + lq0 + qq][b][pp0] = mag;
    }
}

// ---------------- kernel 6: softmax over b (sums AC + BD) ----------------
__global__ __launch_bounds__(256) void k_softmax()
{
    int idx = blockIdx.x * 256 + threadIdx.x;
    int p  = idx % P_;
    int q  = (idx / P_) % Q_;
    int hn = idx / (P_ * Q_);
    size_t off = (((size_t)hn * Q_ + q) * B_) * P_ + p;
    float* baseA = &g_S[0][0][0][0][0] + off;
    const float* baseB = &g_S2[0][0][0][0][0] + off;
    float v0 = (baseA[0 * P_] + baseB[0 * P_]) * TEMPF;
    float v1 = (baseA[1 * P_] + baseB[1 * P_]) * TEMPF;
    float v2 = (baseA[2 * P_] + baseB[2 * P_]) * TEMPF;
    float v3 = (baseA[3 * P_] + baseB[3 * P_]) * TEMPF;
    float m = fmaxf(fmaxf(v0, v1), fmaxf(v2, v3));
    v0 = __expf(v0 - m); v1 = __expf(v1 - m); v2 = __expf(v2 - m); v3 = __expf(v3 - m);
    float inv = 1.f / (v0 + v1 + v2 + v3);
    baseA[0 * P_] = v0 * inv;
    baseA[1 * P_] = v1 * inv;
    baseA[2 * P_] = v2 * inv;
    baseA[3 * P_] = v3 * inv;
}

// ---------------- kernel 7: output aggregation, 4q x 8d tiles ----------------
// grid (2 q-halves of 64, B, H*N), block 128: tx(8)->8d, ty(16)->4q
__global__ __launch_bounds__(128) void k_out(
    const float* __restrict__ vr, const float* __restrict__ vi,
    float* __restrict__ out)
{
    int b = blockIdx.y;
    int h = blockIdx.z / N_, n = blockIdx.z % N_;
    int q0 = blockIdx.x * 64;

    extern __shared__ float sm_o[];
    float* aff_s = sm_o;                  // [64 q][64 p-chunk]
    float* vr_s  = aff_s + 64 * 64;       // [64 p][64 d]
    float* vi_s  = vr_s + 64 * 64;

    int t = threadIdx.x;
    int tx = t & 7, ty = t >> 3;
    int d0 = tx * 8, lq0 = ty * 4;

    float2 cr[4][4], ci[4][4];
#pragma unroll
    for (int qq = 0; qq < 4; qq++)
#pragma unroll
        for (int j = 0; j < 4; j++) { cr[qq][j] = make_float2(0.f, 0.f); ci[qq][j] = make_float2(0.f, 0.f); }

    for (int c = 0; c < 2; c++) {
        __syncthreads();
        int p0 = c * 64;
        for (int i = t; i < 64 * 16; i += 128) {
            int lq = i >> 4, pp4 = i & 15;
            ((float4*)(aff_s + lq * 64))[pp4] =
                *(const float4*)&g_S[h][n][q0 + lq][b][p0 + pp4 * 4];
        }
        for (int i = t; i < 64 * 16; i += 128) {
            int pp = i >> 4, d4 = i & 15;
            size_t off = ((((size_t)n * P_ + p0 + pp) * B_ + b) * D_) / 4 + d4;
            ((float4*)(vr_s + pp * 64))[d4] = ((const float4*)vr)[off];
            ((float4*)(vi_s + pp * 64))[d4] = ((const float4*)vi)[off];
        }
        __syncthreads();

#pragma unroll 4
        for (int pp = 0; pp < 64; pp++) {
            float4 a0 = *(const float4*)&vr_s[pp * 64 + d0];
            float4 a1 = *(const float4*)&vr_s[pp * 64 + d0 + 4];
            float4 b0 = *(const float4*)&vi_s[pp * 64 + d0];
            float4 b1 = *(const float4*)&vi_s[pp * 64 + d0 + 4];
            float2 vrp[4] = { make_float2(a0.x, a0.y), make_float2(a0.z, a0.w),
                              make_float2(a1.x, a1.y), make_float2(a1.z, a1.w) };
            float2 vip[4] = { make_float2(b0.x, b0.y), make_float2(b0.z, b0.w),
                              make_float2(b1.x, b1.y), make_float2(b1.z, b1.w) };
#pragma unroll
            for (int qq = 0; qq < 4; qq++) {
                float2 a2 = dup2(aff_s[(lq0 + qq) * 64 + pp]);
#pragma unroll
                for (int j = 0; j < 4; j++) {
                    fma2(cr[qq][j], a2, vrp[j]);
                    fma2(ci[qq][j], a2, vip[j]);
                }
            }
        }
    }

#pragma unroll
    for (int qq = 0; qq < 4; qq++) {
        int qg = q0 + lq0 + qq;
        size_t o = (((size_t)n * Q_ + qg) * B_ + b) * (H_ * D_) + h * D_ + d0;
        *(float4*)(out + o)     = make_float4(cr[qq][0].x, cr[qq][0].y, cr[qq][1].x, cr[qq][1].y);
        *(float4*)(out + o + 4) = make_float4(cr[qq][2].x, cr[qq][2].y, cr[qq][3].x, cr[qq][3].y);
        size_t oi = o + (size_t)N_ * Q_ * B_ * H_ * D_;
        *(float4*)(out + oi)     = make_float4(ci[qq][0].x, ci[qq][0].y, ci[qq][1].x, ci[qq][1].y);
        *(float4*)(out + oi + 4) = make_float4(ci[qq][2].x, ci[qq][2].y, ci[qq][3].x, ci[qq][3].y);
    }
}

// ---------------- launch ----------------
extern "C" void kernel_launch(void* const* d_in, const int* in_sizes, int n_in,
                              void* d_out, int out_size)
{
    const float* query_r = (const float*)d_in[0];
    const float* query_i = (const float*)d_in[1];
    const float* key_r   = (const float*)d_in[2];
    const float* key_i   = (const float*)d_in[3];
    const float* val_r   = (const float*)d_in[4];
    const float* val_i   = (const float*)d_in[5];
    const float* emb_r   = (const float*)d_in[6];
    const float* emb_i   = (const float*)d_in[7];
    const float* WKr_w   = (const float*)d_in[8];
    const float* WKr_b   = (const float*)d_in[9];
    const float* WKi_w   = (const float*)d_in[10];
    const float* WKi_b   = (const float*)d_in[11];
    const float* WKRr_w  = (const float*)d_in[12];
    const float* WKRr_b  = (const float*)d_in[13];
    const float* WKRi_w  = (const float*)d_in[14];
    const float* WKRi_b  = (const float*)d_in[15];
    const float* WQr_w   = (const float*)d_in[16];
    const float* WQr_b   = (const float*)d_in[17];
    const float* WQi_w   = (const float*)d_in[18];
    const float* WQi_b   = (const float*)d_in[19];
    const float* ww_r_g  = (const float*)d_in[20];
    const float* ww_r_bt = (const float*)d_in[21];
    const float* ww_i_g  = (const float*)d_in[22];
    const float* ww_i_bt = (const float*)d_in[23];
    const float* wr_r_g  = (const float*)d_in[24];
    const float* wr_r_bt = (const float*)d_in[25];
    const float* wr_i_g  = (const float*)d_in[26];
    const float* wr_i_bt = (const float*)d_in[27];

    cudaFuncSetAttribute(k_proj, cudaFuncAttributeMaxDynamicSharedMemorySize, SMEM_PROJ);
    cudaFuncSetAttribute(k_tvec, cudaFuncAttributeMaxDynamicSharedMemorySize, SMEM_TVEC);
    cudaFuncSetAttribute(k_bd,   cudaFuncAttributeMaxDynamicSharedMemorySize, SMEM_BD);
    cudaFuncSetAttribute(k_ac,   cudaFuncAttributeMaxDynamicSharedMemorySize, SMEM_AC);
    cudaFuncSetAttribute(k_out,  cudaFuncAttributeMaxDynamicSharedMemorySize, SMEM_OUT);

    k_proj<<<dim3(16, H_, 2), 128, SMEM_PROJ>>>(key_r, key_i, query_r, query_i,
                                                WKr_w, WKr_b, WKi_w, WKi_b,
                                                WQr_w, WQr_b, WQi_w, WQi_b);
    k_stats<<<dim3(N_, H_, 4), 512>>>();
    k_tvec<<<dim3(32, H_), 128, SMEM_TVEC>>>(WKRr_w, WKRr_b, WKRi_w, WKRi_b,
                                             wr_r_g, wr_r_bt, wr_i_g, wr_i_bt);
    k_bd<<<ROWS_, 256, SMEM_BD>>>((const float4*)emb_r, (const float4*)emb_i);
    k_ac<<<dim3(4, B_, H_ * N_), 256, SMEM_AC>>>(ww_r_g, ww_r_bt, ww_i_g, ww_i_bt);
    k_softmax<<<1024, 256>>>();
    k_out<<<dim3(2, B_, H_ * N_), 128, SMEM_OUT>>>(val_r, val_i, (float*)d_out);
}